// round 2
// baseline (speedup 1.0000x reference)
#include <cuda_runtime.h>
#include <cuda_bf16.h>
#include <math.h>

// Problem constants (fixed for this problem instance)
#define D_IN   256
#define H_HID  128
#define TM     64          // rows per tile in K1
#define K1_THREADS 512
#define XS_STRIDE 260      // 256 + 4 pad (keeps float4 alignment)
#define N_MAX  302080
#define B_MAX  512

// Scratch (device globals: no allocation allowed)
__device__ float g_scores[N_MAX];
__device__ float g_stats[2];   // [0] = global max, [1] = sum of exp
__device__ int   g_batch64;    // 1 if batch buffer is int64, 0 if int32

// ---------------------------------------------------------------------------
// K0: zero output, init softmax stats, detect batch dtype.
// int64 layout: index N-1 (odd) is the HIGH word of an element -> 0.
// int32 layout: index N-1 is the last sorted batch id -> ~511 (nonzero).
// ---------------------------------------------------------------------------
__global__ void k0_init(float* __restrict__ out, int out_size,
                        const int* __restrict__ batch_raw, int N)
{
    int idx = blockIdx.x * blockDim.x + threadIdx.x;
    int stride = gridDim.x * blockDim.x;
    for (int i = idx; i < out_size; i += stride) out[i] = 0.0f;
    if (idx == 0) {
        g_stats[0] = -1e30f;
        g_stats[1] = 0.0f;
        g_batch64 = (batch_raw[N - 1] == 0) ? 1 : 0;
    }
}

// ---------------------------------------------------------------------------
// K1: scores[i] = relu(x[i,:] @ W1 + b1) @ W2   (b2 dropped: softmax-invariant)
// Persistent blocks, W1 cached in smem once per block, x tiles staged in smem,
// 2x8 register blocking per thread.
// ---------------------------------------------------------------------------
extern __shared__ float k1_smem[];

__global__ __launch_bounds__(K1_THREADS, 1)
void k1_scores(const float* __restrict__ x,
               const float* __restrict__ W1,
               const float* __restrict__ b1,
               const float* __restrict__ W2,
               int N)
{
    float* W1s = k1_smem;                   // [256][128]
    float* xs  = k1_smem + D_IN * H_HID;    // [64][260]

    int tid  = threadIdx.x;
    int tidx = tid & 15;        // 16 column groups
    int tidy = tid >> 4;        // 32 row-pair groups
    int c0   = tidx * 8;        // first of 8 hidden columns owned by this thread

    // Load W1 into smem (once per block)
    for (int i = tid; i < (D_IN * H_HID) / 4; i += K1_THREADS)
        ((float4*)W1s)[i] = ((const float4*)W1)[i];

    float b1f[8], W2f[8];
#pragma unroll
    for (int j = 0; j < 8; j++) {
        b1f[j] = __ldg(b1 + c0 + j);
        W2f[j] = __ldg(W2 + c0 + j);
    }

    int ntiles = (N + TM - 1) / TM;
    for (int tile = blockIdx.x; tile < ntiles; tile += gridDim.x) {
        int row0 = tile * TM;

        __syncthreads();  // protect xs reuse (orders W1s load on first iter)

        for (int i = tid; i < TM * (D_IN / 4); i += K1_THREADS) {
            int r  = i >> 6;          // D_IN/4 == 64
            int k4 = i & 63;
            int gr = row0 + r;
            float4 v = make_float4(0.f, 0.f, 0.f, 0.f);
            if (gr < N) v = ((const float4*)(x + (size_t)gr * D_IN))[k4];
            *((float4*)(xs + r * XS_STRIDE + k4 * 4)) = v;
        }
        __syncthreads();

        float acc[2][8];
#pragma unroll
        for (int i = 0; i < 2; i++)
#pragma unroll
            for (int j = 0; j < 8; j++) acc[i][j] = 0.0f;

        const float* xr0 = xs + (tidy * 2 + 0) * XS_STRIDE;
        const float* xr1 = xs + (tidy * 2 + 1) * XS_STRIDE;

#pragma unroll 8
        for (int k = 0; k < D_IN; k++) {
            float x0 = xr0[k];
            float x1 = xr1[k];
            float4 w0 = *((const float4*)(W1s + k * H_HID + c0));
            float4 w1 = *((const float4*)(W1s + k * H_HID + c0 + 4));
            float wv[8] = {w0.x, w0.y, w0.z, w0.w, w1.x, w1.y, w1.z, w1.w};
#pragma unroll
            for (int j = 0; j < 8; j++) {
                acc[0][j] = fmaf(x0, wv[j], acc[0][j]);
                acc[1][j] = fmaf(x1, wv[j], acc[1][j]);
            }
        }

        // Epilogue: relu + dot with W2, reduce across the 16 tidx lanes
#pragma unroll
        for (int i = 0; i < 2; i++) {
            float p = 0.0f;
#pragma unroll
            for (int j = 0; j < 8; j++) {
                float h = acc[i][j] + b1f[j];
                h = h > 0.0f ? h : 0.0f;
                p = fmaf(h, W2f[j], p);
            }
#pragma unroll
            for (int m = 8; m >= 1; m >>= 1)
                p += __shfl_xor_sync(0xffffffffu, p, m);
            int gr = row0 + tidy * 2 + i;
            if (tidx == 0 && gr < N) g_scores[gr] = p;
        }
    }
}

// ---------------------------------------------------------------------------
// Softmax passes over scores
// ---------------------------------------------------------------------------
__device__ void atomicMaxFloat(float* addr, float v)
{
    int* ai  = (int*)addr;
    int  old = *ai;
    while (__int_as_float(old) < v) {
        int assumed = old;
        old = atomicCAS(ai, assumed, __float_as_int(v));
        if (old == assumed) break;
    }
}

__global__ void k2_max(int N)
{
    float m = -1e30f;
    int idx = blockIdx.x * blockDim.x + threadIdx.x;
    int stride = gridDim.x * blockDim.x;
    for (int i = idx; i < N; i += stride) m = fmaxf(m, g_scores[i]);
#pragma unroll
    for (int o = 16; o >= 1; o >>= 1)
        m = fmaxf(m, __shfl_xor_sync(0xffffffffu, m, o));
    __shared__ float s[8];
    int warp = threadIdx.x >> 5, lane = threadIdx.x & 31;
    if (lane == 0) s[warp] = m;
    __syncthreads();
    if (warp == 0) {
        m = (lane < (blockDim.x >> 5)) ? s[lane] : -1e30f;
#pragma unroll
        for (int o = 4; o >= 1; o >>= 1)
            m = fmaxf(m, __shfl_xor_sync(0xffffffffu, m, o));
        if (lane == 0) atomicMaxFloat(&g_stats[0], m);
    }
}

__global__ void k3_sumexp(int N)
{
    float gm = g_stats[0];
    float acc = 0.0f;
    int idx = blockIdx.x * blockDim.x + threadIdx.x;
    int stride = gridDim.x * blockDim.x;
    for (int i = idx; i < N; i += stride) acc += expf(g_scores[i] - gm);
#pragma unroll
    for (int o = 16; o >= 1; o >>= 1)
        acc += __shfl_xor_sync(0xffffffffu, acc, o);
    __shared__ float s[8];
    int warp = threadIdx.x >> 5, lane = threadIdx.x & 31;
    if (lane == 0) s[warp] = acc;
    __syncthreads();
    if (warp == 0) {
        acc = (lane < (blockDim.x >> 5)) ? s[lane] : 0.0f;
#pragma unroll
        for (int o = 4; o >= 1; o >>= 1)
            acc += __shfl_xor_sync(0xffffffffu, acc, o);
        if (lane == 0) atomicAdd(&g_stats[1], acc);
    }
}

__global__ void k3b_weights(int N)
{
    float gm = g_stats[0];
    float rz = 1.0f / g_stats[1];
    int idx = blockIdx.x * blockDim.x + threadIdx.x;
    int stride = gridDim.x * blockDim.x;
    for (int i = idx; i < N; i += stride)
        g_scores[i] = expf(g_scores[i] - gm) * rz;   // in-place: scores -> weights
}

// ---------------------------------------------------------------------------
// K4: pooled[batch[i], :] += x[i, :] * w[i]   (batch sorted)
// One thread per column; register accumulation; atomics only at segment /
// chunk boundaries. dtype-agnostic batch read via g_batch64 flag.
// ---------------------------------------------------------------------------
__device__ __forceinline__ long long read_batch(const void* batch, long long r,
                                                int is64)
{
    if (is64) return ((const long long*)batch)[r];
    return (long long)((const int*)batch)[r];
}

__global__ __launch_bounds__(D_IN)
void k4_pool(const float* __restrict__ x,
             const void* __restrict__ batch,
             float* __restrict__ out,
             int N, int out_size)
{
    int c = threadIdx.x;                       // column 0..255
    int is64 = g_batch64;
    long long nb    = gridDim.x;
    long long chunk = ((long long)N + nb - 1) / nb;
    long long r0 = (long long)blockIdx.x * chunk;
    long long r1 = r0 + chunk;
    if (r1 > N) r1 = N;
    if (r0 >= r1) return;

    long long cur = read_batch(batch, r0, is64);
    float acc = 0.0f;
    for (long long r = r0; r < r1; r++) {
        long long b = read_batch(batch, r, is64);
        if (b != cur) {
            if (cur >= 0 && (cur + 1) * D_IN <= out_size)   // safety bound
                atomicAdd(out + cur * D_IN + c, acc);
            acc = 0.0f;
            cur = b;
        }
        acc = fmaf(x[r * D_IN + c], g_scores[r], acc);
    }
    if (cur >= 0 && (cur + 1) * D_IN <= out_size)
        atomicAdd(out + cur * D_IN + c, acc);
}

// ---------------------------------------------------------------------------
// Launch
// ---------------------------------------------------------------------------
extern "C" void kernel_launch(void* const* d_in, const int* in_sizes, int n_in,
                              void* d_out, int out_size)
{
    const float* x = (const float*)d_in[0];
    const void*  batch = d_in[1];
    int N = in_sizes[1];

    // Locate W1 by its unique element count; b1 and W2 follow it in order.
    int iW1 = -1;
    for (int i = 2; i < n_in; i++)
        if (in_sizes[i] == D_IN * H_HID) { iW1 = i; break; }
    if (iW1 < 0) iW1 = 2;   // fallback (shouldn't happen)
    const float* W1 = (const float*)d_in[iW1];
    const float* b1 = (const float*)d_in[iW1 + 1];
    const float* W2 = (const float*)d_in[iW1 + 2];
    // b2 dropped: constant shift is softmax-invariant

    size_t smem_k1 = (size_t)(D_IN * H_HID + TM * XS_STRIDE) * sizeof(float);
    cudaFuncSetAttribute(k1_scores, cudaFuncAttributeMaxDynamicSharedMemorySize,
                         (int)smem_k1);

    k0_init<<<512, 256>>>((float*)d_out, out_size, (const int*)batch, N);
    k1_scores<<<148, K1_THREADS, smem_k1>>>(x, W1, b1, W2, N);
    k2_max<<<592, 256>>>(N);
    k3_sumexp<<<592, 256>>>(N);
    k3b_weights<<<592, 256>>>(N);
    k4_pool<<<2048, D_IN>>>(x, batch, (float*)d_out, N, out_size);
}

// round 4
// speedup vs baseline: 3.2504x; 3.2504x over previous
#include <cuda_runtime.h>
#include <cuda_bf16.h>
#include <math.h>
#include <stdint.h>

// ===========================================================================
// Problem constants
// ===========================================================================
#define D_IN   256
#define H_HID  128
#define TILE_M 128
#define KHALF  128
#define N_MAX  302080
#define K1_THREADS 256

#define XS_STRIDE 136     // bf16 elems per x-smem row (128 + 8 pad)
#define WS_STRIDE 264     // bf16 elems per W1t-smem row (256 + 8 pad)

// SMEM layout (byte offsets into dynamic smem)
#define SM_PS   0                          // 128 floats
#define SM_B1   512                        // 128 floats
#define SM_W2   1024                       // 128 floats
#define SM_XHI  2048                       // 128*136*2 = 34816
#define SM_XLO  (SM_XHI + 34816)
#define SM_WHI  (SM_XLO + 34816)           // 128*264*2 = 67584
#define SM_WLO  (SM_WHI + 67584)
#define SMEM_TOTAL (SM_WLO + 67584)        // 206848 B

// Scratch (device globals: no allocation allowed)
__device__ float g_scores[N_MAX];
__device__ float g_stats[2];   // [0] = global max, [1] = sum of exp
__device__ int   g_batch64;    // 1 if batch buffer is int64, 0 if int32

// ===========================================================================
// Warp MMA: m16n8k16 row.col f32 <- bf16 x bf16 (baseline PTX, sm_80+)
// ===========================================================================
__device__ __forceinline__ void mma_bf16(float* c,
                                         uint32_t a0, uint32_t a1,
                                         uint32_t a2, uint32_t a3,
                                         uint32_t b0, uint32_t b1)
{
    asm volatile(
        "mma.sync.aligned.m16n8k16.row.col.f32.bf16.bf16.f32 "
        "{%0,%1,%2,%3}, {%4,%5,%6,%7}, {%8,%9}, {%0,%1,%2,%3};"
        : "+f"(c[0]), "+f"(c[1]), "+f"(c[2]), "+f"(c[3])
        : "r"(a0), "r"(a1), "r"(a2), "r"(a3), "r"(b0), "r"(b1));
}

// pack two floats into bf16x2 (lo element in low 16 bits), return residuals
__device__ __forceinline__ uint32_t pack_hi(float a, float b, float& ra, float& rb)
{
    __nv_bfloat16 ha = __float2bfloat16(a);
    __nv_bfloat16 hb = __float2bfloat16(b);
    ra = a - __bfloat162float(ha);
    rb = b - __bfloat162float(hb);
    return ((uint32_t)__bfloat16_as_ushort(hb) << 16) | __bfloat16_as_ushort(ha);
}
__device__ __forceinline__ uint32_t pack_lo(float ra, float rb)
{
    __nv_bfloat16 la = __float2bfloat16(ra);
    __nv_bfloat16 lb = __float2bfloat16(rb);
    return ((uint32_t)__bfloat16_as_ushort(lb) << 16) | __bfloat16_as_ushort(la);
}

// ===========================================================================
// K0: zero output, init stats, detect batch dtype
// int64 layout: int-index N-1 (odd) is the HIGH word of an element -> 0.
// int32 layout: it's the last sorted batch id -> ~511 (nonzero).
// ===========================================================================
__global__ void k0_init(float* __restrict__ out, int out_size,
                        const int* __restrict__ batch_raw, int N)
{
    int idx = blockIdx.x * blockDim.x + threadIdx.x;
    int stride = gridDim.x * blockDim.x;
    for (int i = idx; i < out_size; i += stride) out[i] = 0.0f;
    if (idx == 0) {
        g_stats[0] = -1e30f;
        g_stats[1] = 0.0f;
        g_batch64 = (batch_raw[N - 1] == 0) ? 1 : 0;
    }
}

// ===========================================================================
// K1: scores = relu(x @ W1 + b1) @ W2 via warp-mma bf16x3 split precision.
// Persistent 148 CTAs; W1^T hi/lo resident in smem; per 128-row tile the
// two x K-halves are staged hi/lo in smem; 8 warps in 4m x 2n grid,
// warp tile 32m x 64n (2 x 8 mma tiles), fp32 accumulators.
// ===========================================================================
extern __shared__ char k1s[];

__global__ __launch_bounds__(K1_THREADS, 1)
void k1_scores(const float* __restrict__ x,
               const float* __restrict__ W1,
               const float* __restrict__ b1,
               const float* __restrict__ W2,
               int N)
{
    int tid  = threadIdx.x;
    int wid  = tid >> 5;
    int lane = tid & 31;
    int g    = lane >> 2;     // group id 0..7
    int t    = lane & 3;      // thread-in-group 0..3
    int wm   = wid >> 1;      // 0..3  -> rows wm*32
    int wn   = wid & 1;       // 0..1  -> cols wn*64

    float* ps  = (float*)(k1s + SM_PS);
    float* b1s = (float*)(k1s + SM_B1);
    float* W2s = (float*)(k1s + SM_W2);
    __nv_bfloat16* xhi = (__nv_bfloat16*)(k1s + SM_XHI);
    __nv_bfloat16* xlo = (__nv_bfloat16*)(k1s + SM_XLO);
    __nv_bfloat16* whi = (__nv_bfloat16*)(k1s + SM_WHI);
    __nv_bfloat16* wlo = (__nv_bfloat16*)(k1s + SM_WLO);

    if (tid < H_HID) { b1s[tid] = b1[tid]; W2s[tid] = W2[tid]; }

    // --- Convert W1^T into whi/wlo smem (once). wT[n][k] = W1[k*H + n] ---
    for (int i = tid; i < D_IN * H_HID; i += K1_THREADS) {
        int n = i & 127;
        int k = i >> 7;
        float v = W1[k * H_HID + n];
        __nv_bfloat16 h = __float2bfloat16(v);
        whi[n * WS_STRIDE + k] = h;
        wlo[n * WS_STRIDE + k] = __float2bfloat16(v - __bfloat162float(h));
    }
    __syncthreads();

    int ntiles = (N + TILE_M - 1) / TILE_M;

    for (int tile = blockIdx.x; tile < ntiles; tile += gridDim.x) {
        int row0 = tile * TILE_M;

        float C[2][8][4];
#pragma unroll
        for (int mt = 0; mt < 2; mt++)
#pragma unroll
            for (int nt = 0; nt < 8; nt++)
#pragma unroll
                for (int q = 0; q < 4; q++) C[mt][nt][q] = 0.0f;

        for (int half = 0; half < 2; half++) {
            __syncthreads();   // previous fragments consumed; smem reusable

            // Stage x[:, half*128 .. +127] as hi/lo bf16
            for (int i = tid; i < TILE_M * (KHALF / 4); i += K1_THREADS) {
                int r  = i >> 5;          // row 0..127
                int c4 = i & 31;          // float4 idx
                int gr = row0 + r;
                float4 v = make_float4(0.f, 0.f, 0.f, 0.f);
                if (gr < N)
                    v = ((const float4*)(x + (size_t)gr * D_IN + half * KHALF))[c4];
                float rx, ry, rz, rw;
                uint32_t h01 = pack_hi(v.x, v.y, rx, ry);
                uint32_t h23 = pack_hi(v.z, v.w, rz, rw);
                uint32_t l01 = pack_lo(rx, ry);
                uint32_t l23 = pack_lo(rz, rw);
                int e = r * XS_STRIDE + c4 * 4;
                *(uint32_t*)(xhi + e)     = h01;
                *(uint32_t*)(xhi + e + 2) = h23;
                *(uint32_t*)(xlo + e)     = l01;
                *(uint32_t*)(xlo + e + 2) = l23;
            }
            __syncthreads();

            int kB0 = half * KHALF;    // W1t k-offset for this half

#pragma unroll 2
            for (int ks = 0; ks < 8; ks++) {
                int ka = ks * 16;          // k offset within half (A)
                int kb = kB0 + ka;         // k offset global (B)

                // A fragments: 2 m-tiles, rows wm*32 + mt*16 + {g, g+8}
                uint32_t AH[2][4], AL[2][4];
#pragma unroll
                for (int mt = 0; mt < 2; mt++) {
                    int rA = wm * 32 + mt * 16 + g;
                    const __nv_bfloat16* pa = xhi + rA * XS_STRIDE + ka + 2 * t;
                    const __nv_bfloat16* pl = xlo + rA * XS_STRIDE + ka + 2 * t;
                    AH[mt][0] = *(const uint32_t*)(pa);
                    AH[mt][1] = *(const uint32_t*)(pa + 8 * XS_STRIDE);
                    AH[mt][2] = *(const uint32_t*)(pa + 8);
                    AH[mt][3] = *(const uint32_t*)(pa + 8 * XS_STRIDE + 8);
                    AL[mt][0] = *(const uint32_t*)(pl);
                    AL[mt][1] = *(const uint32_t*)(pl + 8 * XS_STRIDE);
                    AL[mt][2] = *(const uint32_t*)(pl + 8);
                    AL[mt][3] = *(const uint32_t*)(pl + 8 * XS_STRIDE + 8);
                }

#pragma unroll
                for (int nt = 0; nt < 8; nt++) {
                    int nB = wn * 64 + nt * 8 + g;
                    const __nv_bfloat16* pb = whi + nB * WS_STRIDE + kb + 2 * t;
                    const __nv_bfloat16* pc = wlo + nB * WS_STRIDE + kb + 2 * t;
                    uint32_t BH0 = *(const uint32_t*)(pb);
                    uint32_t BH1 = *(const uint32_t*)(pb + 8);
                    uint32_t BL0 = *(const uint32_t*)(pc);
                    uint32_t BL1 = *(const uint32_t*)(pc + 8);
#pragma unroll
                    for (int mt = 0; mt < 2; mt++) {
                        mma_bf16(C[mt][nt], AH[mt][0], AH[mt][1], AH[mt][2], AH[mt][3], BH0, BH1);
                        mma_bf16(C[mt][nt], AH[mt][0], AH[mt][1], AH[mt][2], AH[mt][3], BL0, BL1);
                        mma_bf16(C[mt][nt], AL[mt][0], AL[mt][1], AL[mt][2], AL[mt][3], BH0, BH1);
                    }
                }
            }
        }

        // --- Epilogue: relu(h + b1) dot W2; rows of this warp: wm*32 + ... ---
        float pA[2], pB[2];
#pragma unroll
        for (int mt = 0; mt < 2; mt++) {
            float pa = 0.0f, pb = 0.0f;
#pragma unroll
            for (int nt = 0; nt < 8; nt++) {
                int c0 = wn * 64 + nt * 8 + 2 * t;
                float bb0 = b1s[c0], bb1 = b1s[c0 + 1];
                float ww0 = W2s[c0], ww1 = W2s[c0 + 1];
                float h;
                h = C[mt][nt][0] + bb0; h = h > 0.f ? h : 0.f; pa = fmaf(h, ww0, pa);
                h = C[mt][nt][1] + bb1; h = h > 0.f ? h : 0.f; pa = fmaf(h, ww1, pa);
                h = C[mt][nt][2] + bb0; h = h > 0.f ? h : 0.f; pb = fmaf(h, ww0, pb);
                h = C[mt][nt][3] + bb1; h = h > 0.f ? h : 0.f; pb = fmaf(h, ww1, pb);
            }
            // reduce across the 4 threads of the quad (same rows, diff cols)
            pa += __shfl_xor_sync(0xffffffffu, pa, 1);
            pa += __shfl_xor_sync(0xffffffffu, pa, 2);
            pb += __shfl_xor_sync(0xffffffffu, pb, 1);
            pb += __shfl_xor_sync(0xffffffffu, pb, 2);
            pA[mt] = pa; pB[mt] = pb;
        }

        if (wn == 1 && t == 0) {
#pragma unroll
            for (int mt = 0; mt < 2; mt++) {
                int rA = wm * 32 + mt * 16 + g;
                ps[rA]     = pA[mt];
                ps[rA + 8] = pB[mt];
            }
        }
        __syncthreads();
        if (wn == 0 && t == 0) {
#pragma unroll
            for (int mt = 0; mt < 2; mt++) {
                int rA = wm * 32 + mt * 16 + g;
                int gA = row0 + rA, gB = gA + 8;
                if (gA < N) g_scores[gA] = pA[mt] + ps[rA];
                if (gB < N) g_scores[gB] = pB[mt] + ps[rA + 8];
            }
        }
    }
}

// ===========================================================================
// Softmax passes
// ===========================================================================
__device__ void atomicMaxFloat(float* addr, float v)
{
    int* ai  = (int*)addr;
    int  old = *ai;
    while (__int_as_float(old) < v) {
        int assumed = old;
        old = atomicCAS(ai, assumed, __float_as_int(v));
        if (old == assumed) break;
    }
}

__global__ void k2_max(int N)
{
    float m = -1e30f;
    int idx = blockIdx.x * blockDim.x + threadIdx.x;
    int stride = gridDim.x * blockDim.x;
    for (int i = idx; i < N; i += stride) m = fmaxf(m, g_scores[i]);
#pragma unroll
    for (int o = 16; o >= 1; o >>= 1)
        m = fmaxf(m, __shfl_xor_sync(0xffffffffu, m, o));
    __shared__ float s[8];
    int warp = threadIdx.x >> 5, lane = threadIdx.x & 31;
    if (lane == 0) s[warp] = m;
    __syncthreads();
    if (warp == 0) {
        m = (lane < (blockDim.x >> 5)) ? s[lane] : -1e30f;
#pragma unroll
        for (int o = 4; o >= 1; o >>= 1)
            m = fmaxf(m, __shfl_xor_sync(0xffffffffu, m, o));
        if (lane == 0) atomicMaxFloat(&g_stats[0], m);
    }
}

__global__ void k3_sumexp(int N)
{
    float gm = g_stats[0];
    float acc = 0.0f;
    int idx = blockIdx.x * blockDim.x + threadIdx.x;
    int stride = gridDim.x * blockDim.x;
    for (int i = idx; i < N; i += stride) acc += expf(g_scores[i] - gm);
#pragma unroll
    for (int o = 16; o >= 1; o >>= 1)
        acc += __shfl_xor_sync(0xffffffffu, acc, o);
    __shared__ float s[8];
    int warp = threadIdx.x >> 5, lane = threadIdx.x & 31;
    if (lane == 0) s[warp] = acc;
    __syncthreads();
    if (warp == 0) {
        acc = (lane < (blockDim.x >> 5)) ? s[lane] : 0.0f;
#pragma unroll
        for (int o = 4; o >= 1; o >>= 1)
            acc += __shfl_xor_sync(0xffffffffu, acc, o);
        if (lane == 0) atomicAdd(&g_stats[1], acc);
    }
}

__global__ void k3b_weights(int N)
{
    float gm = g_stats[0];
    float rz = 1.0f / g_stats[1];
    int idx = blockIdx.x * blockDim.x + threadIdx.x;
    int stride = gridDim.x * blockDim.x;
    for (int i = idx; i < N; i += stride)
        g_scores[i] = expf(g_scores[i] - gm) * rz;
}

// ===========================================================================
// K4: pooled[batch[i], :] += x[i, :] * w[i]   (batch sorted)
// ===========================================================================
__device__ __forceinline__ long long read_batch(const void* batch, long long r,
                                                int is64)
{
    if (is64) return ((const long long*)batch)[r];
    return (long long)((const int*)batch)[r];
}

__global__ __launch_bounds__(D_IN)
void k4_pool(const float* __restrict__ x,
             const void* __restrict__ batch,
             float* __restrict__ out,
             int N, int out_size)
{
    int c = threadIdx.x;
    int is64 = g_batch64;
    long long nb    = gridDim.x;
    long long chunk = ((long long)N + nb - 1) / nb;
    long long r0 = (long long)blockIdx.x * chunk;
    long long r1 = r0 + chunk;
    if (r1 > N) r1 = N;
    if (r0 >= r1) return;

    long long cur = read_batch(batch, r0, is64);
    float acc = 0.0f;
    for (long long r = r0; r < r1; r++) {
        long long b = read_batch(batch, r, is64);
        if (b != cur) {
            if (cur >= 0 && (cur + 1) * D_IN <= out_size)
                atomicAdd(out + cur * D_IN + c, acc);
            acc = 0.0f;
            cur = b;
        }
        acc = fmaf(x[r * D_IN + c], g_scores[r], acc);
    }
    if (cur >= 0 && (cur + 1) * D_IN <= out_size)
        atomicAdd(out + cur * D_IN + c, acc);
}

// ===========================================================================
// Launch
// ===========================================================================
extern "C" void kernel_launch(void* const* d_in, const int* in_sizes, int n_in,
                              void* d_out, int out_size)
{
    const float* x = (const float*)d_in[0];
    const void*  batch = d_in[1];
    int N = in_sizes[1];

    int iW1 = -1;
    for (int i = 2; i < n_in; i++)
        if (in_sizes[i] == D_IN * H_HID) { iW1 = i; break; }
    if (iW1 < 0) iW1 = 2;
    const float* W1 = (const float*)d_in[iW1];
    const float* b1 = (const float*)d_in[iW1 + 1];
    const float* W2 = (const float*)d_in[iW1 + 2];
    // b2 dropped: constant shift is softmax-invariant

    cudaFuncSetAttribute(k1_scores, cudaFuncAttributeMaxDynamicSharedMemorySize,
                         SMEM_TOTAL);

    k0_init<<<512, 256>>>((float*)d_out, out_size, (const int*)batch, N);
    k1_scores<<<148, K1_THREADS, SMEM_TOTAL>>>(x, W1, b1, W2, N);
    k2_max<<<592, 256>>>(N);
    k3_sumexp<<<592, 256>>>(N);
    k3b_weights<<<592, 256>>>(N);
    k4_pool<<<2048, D_IN>>>(x, batch, (float*)d_out, N, out_size);
}

// round 6
// speedup vs baseline: 3.8340x; 1.1795x over previous
#include <cuda_runtime.h>
#include <cuda_fp16.h>
#include <cuda_bf16.h>
#include <math.h>
#include <stdint.h>

// ===========================================================================
// Problem constants
// ===========================================================================
#define D_IN   256
#define H_HID  128
#define TILE_M 128
#define KHALF  128
#define N_MAX  302080
#define K1_THREADS 256

#define XS_STRIDE 136     // fp16 elems per x-smem row (128 + 8 pad)
#define WS_STRIDE 264     // fp16 elems per W1t-smem row (256 + 8 pad)

// SMEM layout (byte offsets into dynamic smem)
#define SM_PS    0                           // 384 floats (3 n-warps x 128 rows)
#define SM_SMAX  1536                        // 1 float (+pad)
#define SM_B1    1568                        // 128 floats
#define SM_W2    2080                        // 128 floats
#define SM_X0    2592                        // 128*136*2 = 34816 B
#define SM_X1    (SM_X0 + 34816)
#define SM_WHI   (SM_X1 + 34816)             // 128*264*2 = 67584 B
#define SM_WLO   (SM_WHI + 67584)
#define SMEM_TOTAL (SM_WLO + 67584)          // 207392 B

// Scratch (device globals: no allocation allowed)
__device__ float g_scores[N_MAX];   // scores, then exp(s-max) after k3
__device__ float g_stats[2];        // [0] = global max, [1] = sum of exp
__device__ int   g_batch64;         // 1 if batch buffer is int64, 0 if int32

// ===========================================================================
// Warp MMA: m16n8k16 row.col f32 <- fp16 x fp16 (baseline PTX, sm_80+)
// ===========================================================================
__device__ __forceinline__ void mma_fp16(float* c,
                                         uint32_t a0, uint32_t a1,
                                         uint32_t a2, uint32_t a3,
                                         uint32_t b0, uint32_t b1)
{
    asm volatile(
        "mma.sync.aligned.m16n8k16.row.col.f32.f16.f16.f32 "
        "{%0,%1,%2,%3}, {%4,%5,%6,%7}, {%8,%9}, {%0,%1,%2,%3};"
        : "+f"(c[0]), "+f"(c[1]), "+f"(c[2]), "+f"(c[3])
        : "r"(a0), "r"(a1), "r"(a2), "r"(a3), "r"(b0), "r"(b1));
}

__device__ void atomicMaxFloat(float* addr, float v)
{
    int* ai  = (int*)addr;
    int  old = *ai;
    while (__int_as_float(old) < v) {
        int assumed = old;
        old = atomicCAS(ai, assumed, __float_as_int(v));
        if (old == assumed) break;
    }
}

// ===========================================================================
// K0: zero output, init stats, detect batch dtype
// int64 layout: int-index N-1 (odd) is the HIGH word of an element -> 0.
// int32 layout: it's the last sorted batch id -> ~511 (nonzero).
// ===========================================================================
__global__ void k0_init(float* __restrict__ out, int out_size,
                        const int* __restrict__ batch_raw, int N)
{
    int idx = blockIdx.x * blockDim.x + threadIdx.x;
    int stride = gridDim.x * blockDim.x;
    for (int i = idx; i < out_size; i += stride) out[i] = 0.0f;
    if (idx == 0) {
        g_stats[0] = -1e30f;
        g_stats[1] = 0.0f;
        g_batch64 = (batch_raw[N - 1] == 0) ? 1 : 0;
    }
}

// ===========================================================================
// K1: scores = relu(x @ W1 + b1) @ W2, warp-mma fp16 (x single, W1 hi/lo).
// Persistent 148 CTAs. W1^T hi/lo fp16 resident in smem. Per 128-row tile:
// double-buffered x staging (fp16), 8 warps in 2m x 4n grid (warp tile
// 64x32), fp32 accumulators. Epilogue folds relu+b1, dot W2, cross-warp
// combine, and global-max tracking.
// ===========================================================================
extern __shared__ char k1s[];

__global__ __launch_bounds__(K1_THREADS, 1)
void k1_scores(const float* __restrict__ x,
               const float* __restrict__ W1,
               const float* __restrict__ b1,
               const float* __restrict__ W2,
               int N)
{
    int tid  = threadIdx.x;
    int wid  = tid >> 5;
    int lane = tid & 31;
    int g    = lane >> 2;     // group id 0..7
    int t    = lane & 3;      // thread-in-group 0..3
    int wm   = wid >> 2;      // 0..1  -> rows wm*64
    int wn   = wid & 3;       // 0..3  -> cols wn*32

    float*  ps   = (float*)(k1s + SM_PS);
    float*  smax = (float*)(k1s + SM_SMAX);
    float*  b1s  = (float*)(k1s + SM_B1);
    float*  W2s  = (float*)(k1s + SM_W2);
    __half* x0   = (__half*)(k1s + SM_X0);
    __half* x1   = (__half*)(k1s + SM_X1);
    __half* whi  = (__half*)(k1s + SM_WHI);
    __half* wlo  = (__half*)(k1s + SM_WLO);

    if (tid < H_HID) { b1s[tid] = b1[tid]; W2s[tid] = W2[tid]; }
    if (tid == 0) *smax = -1e30f;

    // --- Convert W1^T into whi/wlo fp16 smem (once). wT[n][k] = W1[k*H+n] ---
    for (int i = tid; i < D_IN * H_HID; i += K1_THREADS) {
        int n = i & 127;
        int k = i >> 7;
        float v = W1[k * H_HID + n];
        __half h = __float2half_rn(v);
        whi[n * WS_STRIDE + k] = h;
        wlo[n * WS_STRIDE + k] = __float2half_rn(v - __half2float(h));
    }

    int ntiles = (N + TILE_M - 1) / TILE_M;

    // stage helper
    auto stage = [&](int row0, int half, __half* xb) {
        for (int i = tid; i < TILE_M * (KHALF / 4); i += K1_THREADS) {
            int r  = i >> 5;
            int c4 = i & 31;
            int gr = row0 + r;
            float4 v = make_float4(0.f, 0.f, 0.f, 0.f);
            if (gr < N)
                v = ((const float4*)(x + (size_t)gr * D_IN + half * KHALF))[c4];
            __half2 h01 = __floats2half2_rn(v.x, v.y);
            __half2 h23 = __floats2half2_rn(v.z, v.w);
            *(uint2*)(xb + r * XS_STRIDE + c4 * 4) =
                make_uint2(*(uint32_t*)&h01, *(uint32_t*)&h23);
        }
    };

    // prologue: stage first tile's half 0 into x0
    int tile = blockIdx.x;
    if (tile < ntiles) stage(tile * TILE_M, 0, x0);
    __syncthreads();

    float lmax = -1e30f;
    int p = 0;   // buffer parity: buf[p] currently staged/valid

    for (; tile < ntiles; tile += gridDim.x) {
        int row0 = tile * TILE_M;

        float C[4][4][4];
#pragma unroll
        for (int mt = 0; mt < 4; mt++)
#pragma unroll
            for (int nt = 0; nt < 4; nt++)
#pragma unroll
                for (int q = 0; q < 4; q++) C[mt][nt][q] = 0.0f;

        for (int half = 0; half < 2; half++) {
            __half* xb = p ? x1 : x0;

            // prefetch next half (or next tile's half 0) into the other buffer
            int ptile = (half == 0) ? tile : (tile + (int)gridDim.x);
            int phalf = half ^ 1;
            if (ptile < ntiles)
                stage(ptile * TILE_M, phalf, p ? x0 : x1);

            int kB0 = half * KHALF;

#pragma unroll 2
            for (int ks = 0; ks < 8; ks++) {
                int ka = ks * 16;
                int kb = kB0 + ka;

                uint32_t A[4][4];
#pragma unroll
                for (int mt = 0; mt < 4; mt++) {
                    int rA = wm * 64 + mt * 16 + g;
                    const __half* pa = xb + rA * XS_STRIDE + ka + 2 * t;
                    A[mt][0] = *(const uint32_t*)(pa);
                    A[mt][1] = *(const uint32_t*)(pa + 8 * XS_STRIDE);
                    A[mt][2] = *(const uint32_t*)(pa + 8);
                    A[mt][3] = *(const uint32_t*)(pa + 8 * XS_STRIDE + 8);
                }

#pragma unroll
                for (int nt = 0; nt < 4; nt++) {
                    int nB = wn * 32 + nt * 8 + g;
                    const __half* pb = whi + nB * WS_STRIDE + kb + 2 * t;
                    const __half* pc = wlo + nB * WS_STRIDE + kb + 2 * t;
                    uint32_t BH0 = *(const uint32_t*)(pb);
                    uint32_t BH1 = *(const uint32_t*)(pb + 8);
                    uint32_t BL0 = *(const uint32_t*)(pc);
                    uint32_t BL1 = *(const uint32_t*)(pc + 8);
#pragma unroll
                    for (int mt = 0; mt < 4; mt++) {
                        mma_fp16(C[mt][nt], A[mt][0], A[mt][1], A[mt][2], A[mt][3], BH0, BH1);
                        mma_fp16(C[mt][nt], A[mt][0], A[mt][1], A[mt][2], A[mt][3], BL0, BL1);
                    }
                }
            }
            __syncthreads();   // staged buffer complete + mma on xb complete
            p ^= 1;
        }

        // --- Epilogue: relu(h + b1) dot W2, quad reduce, cross-warp combine ---
        float pAv[4], pBv[4];
#pragma unroll
        for (int mt = 0; mt < 4; mt++) {
            float pa = 0.0f, pb = 0.0f;
#pragma unroll
            for (int nt = 0; nt < 4; nt++) {
                int c0 = wn * 32 + nt * 8 + 2 * t;
                float bb0 = b1s[c0], bb1 = b1s[c0 + 1];
                float ww0 = W2s[c0], ww1 = W2s[c0 + 1];
                float h;
                h = C[mt][nt][0] + bb0; h = h > 0.f ? h : 0.f; pa = fmaf(h, ww0, pa);
                h = C[mt][nt][1] + bb1; h = h > 0.f ? h : 0.f; pa = fmaf(h, ww1, pa);
                h = C[mt][nt][2] + bb0; h = h > 0.f ? h : 0.f; pb = fmaf(h, ww0, pb);
                h = C[mt][nt][3] + bb1; h = h > 0.f ? h : 0.f; pb = fmaf(h, ww1, pb);
            }
            pa += __shfl_xor_sync(0xffffffffu, pa, 1);
            pa += __shfl_xor_sync(0xffffffffu, pa, 2);
            pb += __shfl_xor_sync(0xffffffffu, pb, 1);
            pb += __shfl_xor_sync(0xffffffffu, pb, 2);
            pAv[mt] = pa; pBv[mt] = pb;
        }

        if (wn > 0 && t == 0) {
#pragma unroll
            for (int mt = 0; mt < 4; mt++) {
                int rA = wm * 64 + mt * 16 + g;
                ps[(wn - 1) * 128 + rA]     = pAv[mt];
                ps[(wn - 1) * 128 + rA + 8] = pBv[mt];
            }
        }
        __syncthreads();
        if (wn == 0 && t == 0) {
#pragma unroll
            for (int mt = 0; mt < 4; mt++) {
                int rA = wm * 64 + mt * 16 + g;
                float ta = pAv[mt] + ps[rA] + ps[128 + rA] + ps[256 + rA];
                float tb = pBv[mt] + ps[rA + 8] + ps[128 + rA + 8] + ps[256 + rA + 8];
                int gA = row0 + rA, gB = gA + 8;
                if (gA < N) { g_scores[gA] = ta; lmax = fmaxf(lmax, ta); }
                if (gB < N) { g_scores[gB] = tb; lmax = fmaxf(lmax, tb); }
            }
        }
        __syncthreads();   // ps consumed before next tile overwrites
    }

    // --- fold per-CTA max into global max ---
    if (wn == 0 && t == 0) atomicMaxFloat(smax, lmax);
    __syncthreads();
    if (tid == 0) atomicMaxFloat(&g_stats[0], *smax);
}

// ===========================================================================
// K3: u[i] = exp(s[i] - max) written in place; accumulate Z = sum u
// ===========================================================================
__global__ void k3_sumexp(int N)
{
    float gm = g_stats[0];
    float acc = 0.0f;
    int idx = blockIdx.x * blockDim.x + threadIdx.x;
    int stride = gridDim.x * blockDim.x;
    for (int i = idx; i < N; i += stride) {
        float u = expf(g_scores[i] - gm);
        g_scores[i] = u;
        acc += u;
    }
#pragma unroll
    for (int o = 16; o >= 1; o >>= 1)
        acc += __shfl_xor_sync(0xffffffffu, acc, o);
    __shared__ float s[8];
    int warp = threadIdx.x >> 5, lane = threadIdx.x & 31;
    if (lane == 0) s[warp] = acc;
    __syncthreads();
    if (warp == 0) {
        acc = (lane < (blockDim.x >> 5)) ? s[lane] : 0.0f;
#pragma unroll
        for (int o = 4; o >= 1; o >>= 1)
            acc += __shfl_xor_sync(0xffffffffu, acc, o);
        if (lane == 0) atomicAdd(&g_stats[1], acc);
    }
}

// ===========================================================================
// K4: pooled[batch[i], :] += x[i, :] * u[i] / Z   (batch sorted)
// ===========================================================================
__device__ __forceinline__ long long read_batch(const void* batch, long long r,
                                                int is64)
{
    if (is64) return ((const long long*)batch)[r];
    return (long long)((const int*)batch)[r];
}

__global__ __launch_bounds__(D_IN)
void k4_pool(const float* __restrict__ x,
             const void* __restrict__ batch,
             float* __restrict__ out,
             int N, int out_size)
{
    int c = threadIdx.x;
    int is64 = g_batch64;
    float rz = 1.0f / g_stats[1];
    long long nb    = gridDim.x;
    long long chunk = ((long long)N + nb - 1) / nb;
    long long r0 = (long long)blockIdx.x * chunk;
    long long r1 = r0 + chunk;
    if (r1 > N) r1 = N;
    if (r0 >= r1) return;

    long long cur = read_batch(batch, r0, is64);
    float acc = 0.0f;
    for (long long r = r0; r < r1; r++) {
        long long b = read_batch(batch, r, is64);
        if (b != cur) {
            if (cur >= 0 && (cur + 1) * D_IN <= out_size)
                atomicAdd(out + cur * D_IN + c, acc);
            acc = 0.0f;
            cur = b;
        }
        acc = fmaf(x[r * D_IN + c], g_scores[r] * rz, acc);
    }
    if (cur >= 0 && (cur + 1) * D_IN <= out_size)
        atomicAdd(out + cur * D_IN + c, acc);
}

// ===========================================================================
// Launch
// ===========================================================================
extern "C" void kernel_launch(void* const* d_in, const int* in_sizes, int n_in,
                              void* d_out, int out_size)
{
    const float* x = (const float*)d_in[0];
    const void*  batch = d_in[1];
    int N = in_sizes[1];

    int iW1 = -1;
    for (int i = 2; i < n_in; i++)
        if (in_sizes[i] == D_IN * H_HID) { iW1 = i; break; }
    if (iW1 < 0) iW1 = 2;
    const float* W1 = (const float*)d_in[iW1];
    const float* b1 = (const float*)d_in[iW1 + 1];
    const float* W2 = (const float*)d_in[iW1 + 2];
    // b2 dropped: constant shift is softmax-invariant

    cudaFuncSetAttribute(k1_scores, cudaFuncAttributeMaxDynamicSharedMemorySize,
                         SMEM_TOTAL);

    k0_init<<<512, 256>>>((float*)d_out, out_size, (const int*)batch, N);
    k1_scores<<<148, K1_THREADS, SMEM_TOTAL>>>(x, W1, b1, W2, N);
    k3_sumexp<<<592, 256>>>(N);
    k4_pool<<<2048, D_IN>>>(x, batch, (float*)d_out, N, out_size);
}

// round 8
// speedup vs baseline: 5.1258x; 1.3369x over previous
#include <cuda_runtime.h>
#include <cuda_fp16.h>
#include <cuda_bf16.h>
#include <math.h>
#include <stdint.h>

// ===========================================================================
// Problem constants
// ===========================================================================
#define D_IN   256
#define H_HID  128
#define TILE_M 128
#define KHALF  128
#define N_MAX  302080
#define K1_THREADS 256

#define XS_STRIDE 136     // fp16 elems per x-smem row (128 + 8 pad)
#define WS_STRIDE 264     // fp16 elems per W1t-smem row (256 + 8 pad)

// SMEM layout (byte offsets into dynamic smem)
#define SM_PS    0                           // 384 floats (3 n-warps x 128 rows)
#define SM_SMAX  1536                        // 1 float (+pad)
#define SM_B1    1568                        // 128 floats
#define SM_W2    2080                        // 128 floats
#define SM_X0    2592                        // 128*136*2 = 34816 B
#define SM_X1    (SM_X0 + 34816)
#define SM_WHI   (SM_X1 + 34816)             // 128*264*2 = 67584 B
#define SM_WLO   (SM_WHI + 67584)
#define SMEM_TOTAL (SM_WLO + 67584)          // 207392 B

// Scratch (device globals: no allocation allowed)
__device__ float g_scores[N_MAX];   // scores, then exp(s-max) after k3
__device__ float g_stats[2];        // [0] = global max, [1] = sum of exp
__device__ int   g_batch64;         // 1 if batch buffer is int64, 0 if int32

// ===========================================================================
// Warp MMA + ldmatrix (baseline PTX, sm_80+)
// ===========================================================================
__device__ __forceinline__ void mma_fp16(float* c,
                                         uint32_t a0, uint32_t a1,
                                         uint32_t a2, uint32_t a3,
                                         uint32_t b0, uint32_t b1)
{
    asm volatile(
        "mma.sync.aligned.m16n8k16.row.col.f32.f16.f16.f32 "
        "{%0,%1,%2,%3}, {%4,%5,%6,%7}, {%8,%9}, {%0,%1,%2,%3};"
        : "+f"(c[0]), "+f"(c[1]), "+f"(c[2]), "+f"(c[3])
        : "r"(a0), "r"(a1), "r"(a2), "r"(a3), "r"(b0), "r"(b1));
}

__device__ __forceinline__ void ldmatrix_x4(uint32_t* r, uint32_t addr)
{
    asm volatile(
        "ldmatrix.sync.aligned.m8n8.x4.shared.b16 {%0,%1,%2,%3}, [%4];"
        : "=r"(r[0]), "=r"(r[1]), "=r"(r[2]), "=r"(r[3]) : "r"(addr));
}

__device__ void atomicMaxFloat(float* addr, float v)
{
    int* ai  = (int*)addr;
    int  old = *ai;
    while (__int_as_float(old) < v) {
        int assumed = old;
        old = atomicCAS(ai, assumed, __float_as_int(v));
        if (old == assumed) break;
    }
}

// ===========================================================================
// K0: zero output, init stats, detect batch dtype
// int64 layout: int-index N-1 (odd) is the HIGH word of an element -> 0.
// int32 layout: it's the last sorted batch id -> ~511 (nonzero).
// ===========================================================================
__global__ void k0_init(float* __restrict__ out, int out_size,
                        const int* __restrict__ batch_raw, int N)
{
    int idx = blockIdx.x * blockDim.x + threadIdx.x;
    int stride = gridDim.x * blockDim.x;
    for (int i = idx; i < out_size; i += stride) out[i] = 0.0f;
    if (idx == 0) {
        g_stats[0] = -1e30f;
        g_stats[1] = 0.0f;
        g_batch64 = (batch_raw[N - 1] == 0) ? 1 : 0;
    }
}

// ===========================================================================
// K1: scores = relu(x @ W1 + b1) @ W2, warp-mma fp16 (x single, W1 hi/lo).
// Persistent 148 CTAs, W1^T hi/lo fp16 resident in smem, double-buffered x
// staging, 8 warps 2m x 4n, ldmatrix fragment loads, fused max tracking.
// ===========================================================================
extern __shared__ char k1s[];

__global__ __launch_bounds__(K1_THREADS, 1)
void k1_scores(const float* __restrict__ x,
               const float* __restrict__ W1,
               const float* __restrict__ b1,
               const float* __restrict__ W2,
               int N)
{
    int tid  = threadIdx.x;
    int wid  = tid >> 5;
    int lane = tid & 31;
    int g    = lane >> 2;     // group id 0..7
    int t    = lane & 3;      // thread-in-group 0..3
    int wm   = wid >> 2;      // 0..1  -> rows wm*64
    int wn   = wid & 3;       // 0..3  -> cols wn*32

    float*  ps   = (float*)(k1s + SM_PS);
    float*  smax = (float*)(k1s + SM_SMAX);
    float*  b1s  = (float*)(k1s + SM_B1);
    float*  W2s  = (float*)(k1s + SM_W2);
    __half* x0   = (__half*)(k1s + SM_X0);
    __half* x1   = (__half*)(k1s + SM_X1);
    __half* whi  = (__half*)(k1s + SM_WHI);
    __half* wlo  = (__half*)(k1s + SM_WLO);

    uint32_t sbase = (uint32_t)__cvta_generic_to_shared(k1s);

    if (tid < H_HID) { b1s[tid] = b1[tid]; W2s[tid] = W2[tid]; }
    if (tid == 0) *smax = -1e30f;

    // --- Convert W1^T into whi/wlo fp16 smem (once). wT[n][k] = W1[k*H+n] ---
    for (int i = tid; i < D_IN * H_HID; i += K1_THREADS) {
        int n = i & 127;
        int k = i >> 7;
        float v = W1[k * H_HID + n];
        __half h = __float2half_rn(v);
        whi[n * WS_STRIDE + k] = h;
        wlo[n * WS_STRIDE + k] = __float2half_rn(v - __half2float(h));
    }

    // --- ldmatrix per-lane address offsets (bytes, excluding k offset) ---
    int ri = lane & 7;        // row within 8x8 tile
    int q  = lane >> 3;       // quadrant 0..3
    // A x4: quadrants (r0-7,k0),(r8-15,k0),(r0-7,k+8),(r8-15,k+8)
    int a_off[4];
#pragma unroll
    for (int mt = 0; mt < 4; mt++) {
        int row = wm * 64 + mt * 16 + ri + (q & 1) * 8;
        a_off[mt] = row * XS_STRIDE * 2 + ((q >> 1) * 8) * 2;
    }
    // B x4 covering nt pair {2j, 2j+1}: quadrants (nt0,k0),(nt0,k+8),(nt1,k0),(nt1,k+8)
    int b_off[2];
#pragma unroll
    for (int j = 0; j < 2; j++) {
        int nt = 2 * j + (q >> 1);
        int nrow = wn * 32 + nt * 8 + ri;
        b_off[j] = nrow * WS_STRIDE * 2 + ((q & 1) * 8) * 2;
    }

    int ntiles = (N + TILE_M - 1) / TILE_M;

    // stage helper
    auto stage = [&](int row0, int half, __half* xb) {
        for (int i = tid; i < TILE_M * (KHALF / 4); i += K1_THREADS) {
            int r  = i >> 5;
            int c4 = i & 31;
            int gr = row0 + r;
            float4 v = make_float4(0.f, 0.f, 0.f, 0.f);
            if (gr < N)
                v = ((const float4*)(x + (size_t)gr * D_IN + half * KHALF))[c4];
            __half2 h01 = __floats2half2_rn(v.x, v.y);
            __half2 h23 = __floats2half2_rn(v.z, v.w);
            *(uint2*)(xb + r * XS_STRIDE + c4 * 4) =
                make_uint2(*(uint32_t*)&h01, *(uint32_t*)&h23);
        }
    };

    // prologue: stage first tile's half 0 into x0
    int tile = blockIdx.x;
    if (tile < ntiles) stage(tile * TILE_M, 0, x0);
    __syncthreads();

    float lmax = -1e30f;
    int p = 0;   // buffer parity: buf[p] currently staged/valid

    for (; tile < ntiles; tile += gridDim.x) {
        int row0 = tile * TILE_M;

        float C[4][4][4];
#pragma unroll
        for (int mt = 0; mt < 4; mt++)
#pragma unroll
            for (int nt = 0; nt < 4; nt++)
#pragma unroll
                for (int qq = 0; qq < 4; qq++) C[mt][nt][qq] = 0.0f;

        for (int half = 0; half < 2; half++) {
            uint32_t xb_base = sbase + (p ? SM_X1 : SM_X0);

            // prefetch next half (or next tile's half 0) into the other buffer
            int ptile = (half == 0) ? tile : (tile + (int)gridDim.x);
            int phalf = half ^ 1;
            if (ptile < ntiles)
                stage(ptile * TILE_M, phalf, p ? x0 : x1);

            int kB0 = half * KHALF;

#pragma unroll 2
            for (int ks = 0; ks < 8; ks++) {
                int ka = ks * 16;
                int kb = kB0 + ka;

                uint32_t A[4][4];
#pragma unroll
                for (int mt = 0; mt < 4; mt++)
                    ldmatrix_x4(A[mt], xb_base + a_off[mt] + ka * 2);

                uint32_t BH[2][4], BL[2][4];
#pragma unroll
                for (int j = 0; j < 2; j++) {
                    ldmatrix_x4(BH[j], sbase + SM_WHI + b_off[j] + kb * 2);
                    ldmatrix_x4(BL[j], sbase + SM_WLO + b_off[j] + kb * 2);
                }

#pragma unroll
                for (int j = 0; j < 2; j++)
#pragma unroll
                    for (int jj = 0; jj < 2; jj++) {
                        int nt = 2 * j + jj;
                        uint32_t bh0 = BH[j][2 * jj], bh1 = BH[j][2 * jj + 1];
                        uint32_t bl0 = BL[j][2 * jj], bl1 = BL[j][2 * jj + 1];
#pragma unroll
                        for (int mt = 0; mt < 4; mt++) {
                            mma_fp16(C[mt][nt], A[mt][0], A[mt][1], A[mt][2], A[mt][3], bh0, bh1);
                            mma_fp16(C[mt][nt], A[mt][0], A[mt][1], A[mt][2], A[mt][3], bl0, bl1);
                        }
                    }
            }
            __syncthreads();   // staged buffer complete + mma on xb complete
            p ^= 1;
        }

        // --- Epilogue: relu(h + b1) dot W2, quad reduce, cross-warp combine ---
        float pAv[4], pBv[4];
#pragma unroll
        for (int mt = 0; mt < 4; mt++) {
            float pa = 0.0f, pb = 0.0f;
#pragma unroll
            for (int nt = 0; nt < 4; nt++) {
                int c0 = wn * 32 + nt * 8 + 2 * t;
                float bb0 = b1s[c0], bb1 = b1s[c0 + 1];
                float ww0 = W2s[c0], ww1 = W2s[c0 + 1];
                float h;
                h = C[mt][nt][0] + bb0; h = h > 0.f ? h : 0.f; pa = fmaf(h, ww0, pa);
                h = C[mt][nt][1] + bb1; h = h > 0.f ? h : 0.f; pa = fmaf(h, ww1, pa);
                h = C[mt][nt][2] + bb0; h = h > 0.f ? h : 0.f; pb = fmaf(h, ww0, pb);
                h = C[mt][nt][3] + bb1; h = h > 0.f ? h : 0.f; pb = fmaf(h, ww1, pb);
            }
            pa += __shfl_xor_sync(0xffffffffu, pa, 1);
            pa += __shfl_xor_sync(0xffffffffu, pa, 2);
            pb += __shfl_xor_sync(0xffffffffu, pb, 1);
            pb += __shfl_xor_sync(0xffffffffu, pb, 2);
            pAv[mt] = pa; pBv[mt] = pb;
        }

        if (wn > 0 && t == 0) {
#pragma unroll
            for (int mt = 0; mt < 4; mt++) {
                int rA = wm * 64 + mt * 16 + g;
                ps[(wn - 1) * 128 + rA]     = pAv[mt];
                ps[(wn - 1) * 128 + rA + 8] = pBv[mt];
            }
        }
        __syncthreads();
        if (wn == 0 && t == 0) {
#pragma unroll
            for (int mt = 0; mt < 4; mt++) {
                int rA = wm * 64 + mt * 16 + g;
                float ta = pAv[mt] + ps[rA] + ps[128 + rA] + ps[256 + rA];
                float tb = pBv[mt] + ps[rA + 8] + ps[128 + rA + 8] + ps[256 + rA + 8];
                int gA = row0 + rA, gB = gA + 8;
                if (gA < N) { g_scores[gA] = ta; lmax = fmaxf(lmax, ta); }
                if (gB < N) { g_scores[gB] = tb; lmax = fmaxf(lmax, tb); }
            }
        }
        __syncthreads();   // ps consumed before next tile overwrites
    }

    // --- fold per-CTA max into global max ---
    if (wn == 0 && t == 0) atomicMaxFloat(smax, lmax);
    __syncthreads();
    if (tid == 0) atomicMaxFloat(&g_stats[0], *smax);
}

// ===========================================================================
// K3: u[i] = exp(s[i] - max) written in place; accumulate Z = sum u
// ===========================================================================
__global__ void k3_sumexp(int N)
{
    float gm = g_stats[0];
    float acc = 0.0f;
    int idx = blockIdx.x * blockDim.x + threadIdx.x;
    int stride = gridDim.x * blockDim.x;
    for (int i = idx; i < N; i += stride) {
        float u = expf(g_scores[i] - gm);
        g_scores[i] = u;
        acc += u;
    }
#pragma unroll
    for (int o = 16; o >= 1; o >>= 1)
        acc += __shfl_xor_sync(0xffffffffu, acc, o);
    __shared__ float s[8];
    int warp = threadIdx.x >> 5, lane = threadIdx.x & 31;
    if (lane == 0) s[warp] = acc;
    __syncthreads();
    if (warp == 0) {
        acc = (lane < (blockDim.x >> 5)) ? s[lane] : 0.0f;
#pragma unroll
        for (int o = 4; o >= 1; o >>= 1)
            acc += __shfl_xor_sync(0xffffffffu, acc, o);
        if (lane == 0) atomicAdd(&g_stats[1], acc);
    }
}

// ===========================================================================
// K4: pooled[batch[i], :] += x[i, :] * u[i] / Z   (batch sorted)
// Row loop unrolled x4 with front-batched independent loads (MLP ~4).
// ===========================================================================
__device__ __forceinline__ int read_batch_i(const void* batch, int r, int is64)
{
    if (is64) return (int)((const long long*)batch)[r];
    return ((const int*)batch)[r];
}

__global__ __launch_bounds__(D_IN)
void k4_pool(const float* __restrict__ x,
             const void* __restrict__ batch,
             float* __restrict__ out,
             int N, int out_size)
{
    int c = threadIdx.x;
    int is64 = g_batch64;
    float rz = 1.0f / g_stats[1];
    int nb    = gridDim.x;
    int chunk = (N + nb - 1) / nb;
    int r0 = blockIdx.x * chunk;
    int r1 = r0 + chunk;
    if (r1 > N) r1 = N;
    if (r0 >= r1) return;
    int nseg = out_size / D_IN;

    int cur = read_batch_i(batch, r0, is64);
    float acc = 0.0f;

#define FLUSH() do { \
        if ((unsigned)cur < (unsigned)nseg) \
            atomicAdd(out + (size_t)cur * D_IN + c, acc); \
        acc = 0.0f; \
    } while (0)

    int r = r0;
    for (; r + 4 <= r1; r += 4) {
        // front-batched independent loads
        float xv0 = x[(size_t)(r + 0) * D_IN + c];
        float xv1 = x[(size_t)(r + 1) * D_IN + c];
        float xv2 = x[(size_t)(r + 2) * D_IN + c];
        float xv3 = x[(size_t)(r + 3) * D_IN + c];
        float w0 = g_scores[r + 0];
        float w1 = g_scores[r + 1];
        float w2 = g_scores[r + 2];
        float w3 = g_scores[r + 3];
        int b0 = read_batch_i(batch, r + 0, is64);
        int b1 = read_batch_i(batch, r + 1, is64);
        int b2 = read_batch_i(batch, r + 2, is64);
        int b3 = read_batch_i(batch, r + 3, is64);

        if (b0 != cur) { FLUSH(); cur = b0; }
        acc = fmaf(xv0, w0 * rz, acc);
        if (b1 != cur) { FLUSH(); cur = b1; }
        acc = fmaf(xv1, w1 * rz, acc);
        if (b2 != cur) { FLUSH(); cur = b2; }
        acc = fmaf(xv2, w2 * rz, acc);
        if (b3 != cur) { FLUSH(); cur = b3; }
        acc = fmaf(xv3, w3 * rz, acc);
    }
    for (; r < r1; r++) {
        float xv = x[(size_t)r * D_IN + c];
        float w  = g_scores[r];
        int b = read_batch_i(batch, r, is64);
        if (b != cur) { FLUSH(); cur = b; }
        acc = fmaf(xv, w * rz, acc);
    }
    FLUSH();
#undef FLUSH
}

// ===========================================================================
// Launch
// ===========================================================================
extern "C" void kernel_launch(void* const* d_in, const int* in_sizes, int n_in,
                              void* d_out, int out_size)
{
    const float* x = (const float*)d_in[0];
    const void*  batch = d_in[1];
    int N = in_sizes[1];

    int iW1 = -1;
    for (int i = 2; i < n_in; i++)
        if (in_sizes[i] == D_IN * H_HID) { iW1 = i; break; }
    if (iW1 < 0) iW1 = 2;
    const float* W1 = (const float*)d_in[iW1];
    const float* b1 = (const float*)d_in[iW1 + 1];
    const float* W2 = (const float*)d_in[iW1 + 2];
    // b2 dropped: constant shift is softmax-invariant

    cudaFuncSetAttribute(k1_scores, cudaFuncAttributeMaxDynamicSharedMemorySize,
                         SMEM_TOTAL);

    k0_init<<<512, 256>>>((float*)d_out, out_size, (const int*)batch, N);
    k1_scores<<<148, K1_THREADS, SMEM_TOTAL>>>(x, W1, b1, W2, N);
    k3_sumexp<<<592, 256>>>(N);
    k4_pool<<<2048, D_IN>>>(x, batch, (float*)d_out, N, out_size);
}

// round 9
// speedup vs baseline: 7.6667x; 1.4957x over previous
#include <cuda_runtime.h>
#include <cuda_fp16.h>
#include <cuda_bf16.h>
#include <math.h>
#include <stdint.h>

// ===========================================================================
// Problem constants
// ===========================================================================
#define D_IN   256
#define H_HID  128
#define TILE_M 128
#define KHALF  128
#define N_MAX  302080
#define K1_THREADS 256

#define XS_STRIDE 136     // fp16 elems per x-smem row (128 + 8 pad)
#define WS_STRIDE 264     // fp16 elems per W1t-smem row (256 + 8 pad)

// SMEM layout (byte offsets into dynamic smem)
#define SM_PS    0                           // 384 floats (3 n-warps x 128 rows)
#define SM_SMAX  1536                        // 1 float (+pad)
#define SM_B1    1568                        // 128 floats
#define SM_W2    2080                        // 128 floats
#define SM_XF    2592                        // fp16 x tile: 128*136*2 = 34816 B
#define SM_WHI   (SM_XF + 34816)             // 128*264*2 = 67584 B
#define SM_RAW   (SM_WHI + 67584)            // raw fp32 half-tile: 128*128*4 = 65536 B
#define SMEM_TOTAL (SM_RAW + 65536)          // ~170.5 KB

// Scratch (device globals: no allocation allowed)
__device__ float g_scores[N_MAX];   // scores, then exp(s-max) after k3
__device__ float g_stats[2];        // [0] = global max, [1] = sum of exp
__device__ int   g_batch64;         // 1 if batch buffer is int64, 0 if int32

// ===========================================================================
// Warp MMA + ldmatrix + cp.async (baseline PTX, sm_80+)
// ===========================================================================
__device__ __forceinline__ void mma_fp16(float* c,
                                         uint32_t a0, uint32_t a1,
                                         uint32_t a2, uint32_t a3,
                                         uint32_t b0, uint32_t b1)
{
    asm volatile(
        "mma.sync.aligned.m16n8k16.row.col.f32.f16.f16.f32 "
        "{%0,%1,%2,%3}, {%4,%5,%6,%7}, {%8,%9}, {%0,%1,%2,%3};"
        : "+f"(c[0]), "+f"(c[1]), "+f"(c[2]), "+f"(c[3])
        : "r"(a0), "r"(a1), "r"(a2), "r"(a3), "r"(b0), "r"(b1));
}

__device__ __forceinline__ void ldmatrix_x4(uint32_t* r, uint32_t addr)
{
    asm volatile(
        "ldmatrix.sync.aligned.m8n8.x4.shared.b16 {%0,%1,%2,%3}, [%4];"
        : "=r"(r[0]), "=r"(r[1]), "=r"(r[2]), "=r"(r[3]) : "r"(addr));
}

#define CP_ASYNC16(dst, src) \
    asm volatile("cp.async.cg.shared.global [%0], [%1], 16;" \
                 :: "r"(dst), "l"(src) : "memory")
#define CP_COMMIT()  asm volatile("cp.async.commit_group;" ::: "memory")
#define CP_WAIT0()   asm volatile("cp.async.wait_group 0;" ::: "memory")

__device__ void atomicMaxFloat(float* addr, float v)
{
    int* ai  = (int*)addr;
    int  old = *ai;
    while (__int_as_float(old) < v) {
        int assumed = old;
        old = atomicCAS(ai, assumed, __float_as_int(v));
        if (old == assumed) break;
    }
}

// ===========================================================================
// K0: zero output, init stats, detect batch dtype
// int64 layout: int-index N-1 (odd) is the HIGH word of an element -> 0.
// int32 layout: it's the last sorted batch id -> ~511 (nonzero).
// ===========================================================================
__global__ void k0_init(float* __restrict__ out, int out_size,
                        const int* __restrict__ batch_raw, int N)
{
    int idx = blockIdx.x * blockDim.x + threadIdx.x;
    int stride = gridDim.x * blockDim.x;
    for (int i = idx; i < out_size; i += stride) out[i] = 0.0f;
    if (idx == 0) {
        g_stats[0] = -1e30f;
        g_stats[1] = 0.0f;
        g_batch64 = (batch_raw[N - 1] == 0) ? 1 : 0;
    }
}

// ===========================================================================
// K1: scores = relu(x @ W1 + b1) @ W2, warp-mma fp16 (x fp16, W1 fp16).
// Persistent 148 CTAs. Pipeline per half-tile:
//   cp.async raw fp32 x (issued during PREVIOUS half's MMAs, latency hidden)
//   -> convert raw (smem) to fp16 tile (smem)  [cheap LDS/STS]
//   -> ldmatrix + 16 HMMA per k-step.
// 8 warps 2m x 4n; epilogue folds relu+b1, dot W2, combine, max tracking.
// ===========================================================================
extern __shared__ char k1s[];

__global__ __launch_bounds__(K1_THREADS, 1)
void k1_scores(const float* __restrict__ x,
               const float* __restrict__ W1,
               const float* __restrict__ b1,
               const float* __restrict__ W2,
               int N)
{
    int tid  = threadIdx.x;
    int wid  = tid >> 5;
    int lane = tid & 31;
    int g    = lane >> 2;     // group id 0..7
    int t    = lane & 3;      // thread-in-group 0..3
    int wm   = wid >> 2;      // 0..1  -> rows wm*64
    int wn   = wid & 3;       // 0..3  -> cols wn*32

    float*  ps   = (float*)(k1s + SM_PS);
    float*  smax = (float*)(k1s + SM_SMAX);
    float*  b1s  = (float*)(k1s + SM_B1);
    float*  W2s  = (float*)(k1s + SM_W2);
    __half* xf   = (__half*)(k1s + SM_XF);
    __half* whi  = (__half*)(k1s + SM_WHI);
    float*  raw  = (float*)(k1s + SM_RAW);

    uint32_t sbase = (uint32_t)__cvta_generic_to_shared(k1s);

    if (tid < H_HID) { b1s[tid] = b1[tid]; W2s[tid] = W2[tid]; }
    if (tid == 0) *smax = -1e30f;

    // --- Convert W1^T into whi fp16 smem (once). wT[n][k] = W1[k*H+n] ---
    for (int i = tid; i < D_IN * H_HID; i += K1_THREADS) {
        int n = i & 127;
        int k = i >> 7;
        whi[n * WS_STRIDE + k] = __float2half_rn(W1[k * H_HID + n]);
    }

    // --- ldmatrix per-lane address offsets (bytes, excluding k offset) ---
    int ri = lane & 7;        // row within 8x8 tile
    int q  = lane >> 3;       // quadrant 0..3
    int a_off[4];
#pragma unroll
    for (int mt = 0; mt < 4; mt++) {
        int row = wm * 64 + mt * 16 + ri + (q & 1) * 8;
        a_off[mt] = row * XS_STRIDE * 2 + ((q >> 1) * 8) * 2;
    }
    int b_off[2];
#pragma unroll
    for (int j = 0; j < 2; j++) {
        int nt = 2 * j + (q >> 1);
        int nrow = wn * 32 + nt * 8 + ri;
        b_off[j] = nrow * WS_STRIDE * 2 + ((q & 1) * 8) * 2;
    }

    int ntiles = (N + TILE_M - 1) / TILE_M;

    // issue cp.async for a half-tile into raw (16 chunks of 16B per thread)
    auto issue_raw = [&](int row0, int half) {
#pragma unroll
        for (int it = 0; it < (TILE_M * (KHALF / 4)) / K1_THREADS; it++) {
            int i  = it * K1_THREADS + tid;
            int r  = i >> 5;
            int c4 = i & 31;
            int gr = row0 + r;
            uint32_t dst = sbase + SM_RAW + (uint32_t)i * 16;
            if (gr < N) {
                const float* src = x + (size_t)gr * D_IN + half * KHALF + c4 * 4;
                CP_ASYNC16(dst, src);
            } else {
                *(float4*)(raw + i * 4) = make_float4(0.f, 0.f, 0.f, 0.f);
            }
        }
        CP_COMMIT();
    };

    // convert raw fp32 -> xf fp16 (each thread owns the same chunks it issued)
    auto convert = [&]() {
#pragma unroll
        for (int it = 0; it < (TILE_M * (KHALF / 4)) / K1_THREADS; it++) {
            int i  = it * K1_THREADS + tid;
            int r  = i >> 5;
            int c4 = i & 31;
            float4 v = *(const float4*)(raw + i * 4);
            __half2 h01 = __floats2half2_rn(v.x, v.y);
            __half2 h23 = __floats2half2_rn(v.z, v.w);
            *(uint2*)(xf + r * XS_STRIDE + c4 * 4) =
                make_uint2(*(uint32_t*)&h01, *(uint32_t*)&h23);
        }
    };

    // prologue: start loading first half-tile
    int tile = blockIdx.x;
    if (tile < ntiles) issue_raw(tile * TILE_M, 0);

    float lmax = -1e30f;

    for (; tile < ntiles; tile += gridDim.x) {
        int row0 = tile * TILE_M;

        float C[4][4][4];
#pragma unroll
        for (int mt = 0; mt < 4; mt++)
#pragma unroll
            for (int nt = 0; nt < 4; nt++)
#pragma unroll
                for (int qq = 0; qq < 4; qq++) C[mt][nt][qq] = 0.0f;

        for (int half = 0; half < 2; half++) {
            // raw[this half] arrived; previous MMA readers of xf are done
            CP_WAIT0();
            __syncthreads();
            convert();
            __syncthreads();   // xf visible to all warps (raw fully consumed)

            // start async load of the NEXT half (raw is free now)
            int ptile = (half == 0) ? tile : (tile + (int)gridDim.x);
            if (ptile < ntiles) issue_raw(ptile * TILE_M, half ^ 1);

            int kB0 = half * KHALF;

#pragma unroll 2
            for (int ks = 0; ks < 8; ks++) {
                int ka = ks * 16;
                int kb = kB0 + ka;

                uint32_t A[4][4];
#pragma unroll
                for (int mt = 0; mt < 4; mt++)
                    ldmatrix_x4(A[mt], sbase + SM_XF + a_off[mt] + ka * 2);

                uint32_t BH[2][4];
#pragma unroll
                for (int j = 0; j < 2; j++)
                    ldmatrix_x4(BH[j], sbase + SM_WHI + b_off[j] + kb * 2);

#pragma unroll
                for (int j = 0; j < 2; j++)
#pragma unroll
                    for (int jj = 0; jj < 2; jj++) {
                        int nt = 2 * j + jj;
                        uint32_t bh0 = BH[j][2 * jj], bh1 = BH[j][2 * jj + 1];
#pragma unroll
                        for (int mt = 0; mt < 4; mt++)
                            mma_fp16(C[mt][nt], A[mt][0], A[mt][1], A[mt][2], A[mt][3], bh0, bh1);
                    }
            }
        }

        // --- Epilogue: relu(h + b1) dot W2, quad reduce, cross-warp combine ---
        float pAv[4], pBv[4];
#pragma unroll
        for (int mt = 0; mt < 4; mt++) {
            float pa = 0.0f, pb = 0.0f;
#pragma unroll
            for (int nt = 0; nt < 4; nt++) {
                int c0 = wn * 32 + nt * 8 + 2 * t;
                float bb0 = b1s[c0], bb1 = b1s[c0 + 1];
                float ww0 = W2s[c0], ww1 = W2s[c0 + 1];
                float h;
                h = C[mt][nt][0] + bb0; h = h > 0.f ? h : 0.f; pa = fmaf(h, ww0, pa);
                h = C[mt][nt][1] + bb1; h = h > 0.f ? h : 0.f; pa = fmaf(h, ww1, pa);
                h = C[mt][nt][2] + bb0; h = h > 0.f ? h : 0.f; pb = fmaf(h, ww0, pb);
                h = C[mt][nt][3] + bb1; h = h > 0.f ? h : 0.f; pb = fmaf(h, ww1, pb);
            }
            pa += __shfl_xor_sync(0xffffffffu, pa, 1);
            pa += __shfl_xor_sync(0xffffffffu, pa, 2);
            pb += __shfl_xor_sync(0xffffffffu, pb, 1);
            pb += __shfl_xor_sync(0xffffffffu, pb, 2);
            pAv[mt] = pa; pBv[mt] = pb;
        }

        if (wn > 0 && t == 0) {
#pragma unroll
            for (int mt = 0; mt < 4; mt++) {
                int rA = wm * 64 + mt * 16 + g;
                ps[(wn - 1) * 128 + rA]     = pAv[mt];
                ps[(wn - 1) * 128 + rA + 8] = pBv[mt];
            }
        }
        __syncthreads();
        if (wn == 0 && t == 0) {
#pragma unroll
            for (int mt = 0; mt < 4; mt++) {
                int rA = wm * 64 + mt * 16 + g;
                float ta = pAv[mt] + ps[rA] + ps[128 + rA] + ps[256 + rA];
                float tb = pBv[mt] + ps[rA + 8] + ps[128 + rA + 8] + ps[256 + rA + 8];
                int gA = row0 + rA, gB = gA + 8;
                if (gA < N) { g_scores[gA] = ta; lmax = fmaxf(lmax, ta); }
                if (gB < N) { g_scores[gB] = tb; lmax = fmaxf(lmax, tb); }
            }
        }
        __syncthreads();   // ps consumed before next tile overwrites
    }

    // --- fold per-CTA max into global max ---
    if (wn == 0 && t == 0) atomicMaxFloat(smax, lmax);
    __syncthreads();
    if (tid == 0) atomicMaxFloat(&g_stats[0], *smax);
}

// ===========================================================================
// K3: u[i] = exp(s[i] - max) written in place; accumulate Z = sum u
// ===========================================================================
__global__ void k3_sumexp(int N)
{
    float gm = g_stats[0];
    float acc = 0.0f;
    int idx = blockIdx.x * blockDim.x + threadIdx.x;
    int stride = gridDim.x * blockDim.x;
    for (int i = idx; i < N; i += stride) {
        float u = expf(g_scores[i] - gm);
        g_scores[i] = u;
        acc += u;
    }
#pragma unroll
    for (int o = 16; o >= 1; o >>= 1)
        acc += __shfl_xor_sync(0xffffffffu, acc, o);
    __shared__ float s[8];
    int warp = threadIdx.x >> 5, lane = threadIdx.x & 31;
    if (lane == 0) s[warp] = acc;
    __syncthreads();
    if (warp == 0) {
        acc = (lane < (blockDim.x >> 5)) ? s[lane] : 0.0f;
#pragma unroll
        for (int o = 4; o >= 1; o >>= 1)
            acc += __shfl_xor_sync(0xffffffffu, acc, o);
        if (lane == 0) atomicAdd(&g_stats[1], acc);
    }
}

// ===========================================================================
// K4: pooled[batch[i], :] += x[i, :] * u[i] / Z   (batch sorted)
// Row loop unrolled x4 with front-batched independent loads (MLP ~4).
// ===========================================================================
__device__ __forceinline__ int read_batch_i(const void* batch, int r, int is64)
{
    if (is64) return (int)((const long long*)batch)[r];
    return ((const int*)batch)[r];
}

__global__ __launch_bounds__(D_IN)
void k4_pool(const float* __restrict__ x,
             const void* __restrict__ batch,
             float* __restrict__ out,
             int N, int out_size)
{
    int c = threadIdx.x;
    int is64 = g_batch64;
    float rz = 1.0f / g_stats[1];
    int nb    = gridDim.x;
    int chunk = (N + nb - 1) / nb;
    int r0 = blockIdx.x * chunk;
    int r1 = r0 + chunk;
    if (r1 > N) r1 = N;
    if (r0 >= r1) return;
    int nseg = out_size / D_IN;

    int cur = read_batch_i(batch, r0, is64);
    float acc = 0.0f;

#define FLUSH() do { \
        if ((unsigned)cur < (unsigned)nseg) \
            atomicAdd(out + (size_t)cur * D_IN + c, acc); \
        acc = 0.0f; \
    } while (0)

    int r = r0;
    for (; r + 4 <= r1; r += 4) {
        float xv0 = x[(size_t)(r + 0) * D_IN + c];
        float xv1 = x[(size_t)(r + 1) * D_IN + c];
        float xv2 = x[(size_t)(r + 2) * D_IN + c];
        float xv3 = x[(size_t)(r + 3) * D_IN + c];
        float w0 = g_scores[r + 0];
        float w1 = g_scores[r + 1];
        float w2 = g_scores[r + 2];
        float w3 = g_scores[r + 3];
        int b0 = read_batch_i(batch, r + 0, is64);
        int b1 = read_batch_i(batch, r + 1, is64);
        int b2 = read_batch_i(batch, r + 2, is64);
        int b3 = read_batch_i(batch, r + 3, is64);

        if (b0 != cur) { FLUSH(); cur = b0; }
        acc = fmaf(xv0, w0 * rz, acc);
        if (b1 != cur) { FLUSH(); cur = b1; }
        acc = fmaf(xv1, w1 * rz, acc);
        if (b2 != cur) { FLUSH(); cur = b2; }
        acc = fmaf(xv2, w2 * rz, acc);
        if (b3 != cur) { FLUSH(); cur = b3; }
        acc = fmaf(xv3, w3 * rz, acc);
    }
    for (; r < r1; r++) {
        float xv = x[(size_t)r * D_IN + c];
        float w  = g_scores[r];
        int b = read_batch_i(batch, r, is64);
        if (b != cur) { FLUSH(); cur = b; }
        acc = fmaf(xv, w * rz, acc);
    }
    FLUSH();
#undef FLUSH
}

// ===========================================================================
// Launch
// ===========================================================================
extern "C" void kernel_launch(void* const* d_in, const int* in_sizes, int n_in,
                              void* d_out, int out_size)
{
    const float* x = (const float*)d_in[0];
    const void*  batch = d_in[1];
    int N = in_sizes[1];

    int iW1 = -1;
    for (int i = 2; i < n_in; i++)
        if (in_sizes[i] == D_IN * H_HID) { iW1 = i; break; }
    if (iW1 < 0) iW1 = 2;
    const float* W1 = (const float*)d_in[iW1];
    const float* b1 = (const float*)d_in[iW1 + 1];
    const float* W2 = (const float*)d_in[iW1 + 2];
    // b2 dropped: constant shift is softmax-invariant

    cudaFuncSetAttribute(k1_scores, cudaFuncAttributeMaxDynamicSharedMemorySize,
                         SMEM_TOTAL);

    k0_init<<<512, 256>>>((float*)d_out, out_size, (const int*)batch, N);
    k1_scores<<<148, K1_THREADS, SMEM_TOTAL>>>(x, W1, b1, W2, N);
    k3_sumexp<<<592, 256>>>(N);
    k4_pool<<<2048, D_IN>>>(x, batch, (float*)d_out, N, out_size);
}

// round 11
// speedup vs baseline: 8.0361x; 1.0482x over previous
#include <cuda_runtime.h>
#include <cuda_fp16.h>
#include <cuda_bf16.h>
#include <math.h>
#include <stdint.h>

// ===========================================================================
// Problem constants
// ===========================================================================
#define D_IN   256
#define H_HID  128
#define TILE_M 128
#define KHALF  128
#define N_MAX  302080
#define K1_THREADS 256

#define XS_STRIDE 136     // fp16 elems per x-smem row (128 + 8 pad)
#define WS_STRIDE 264     // fp16 elems per W1t-smem row (256 + 8 pad)

// SMEM layout (byte offsets into dynamic smem)
#define SM_PS    0                           // 384 floats (3 n-warps x 128 rows)
#define SM_SMAX  1536                        // 1 float (+pad)
#define SM_B1    1568                        // 128 floats
#define SM_W2    2080                        // 128 floats
#define SM_XF    2592                        // fp16 x tile: 128*136*2 = 34816 B
#define SM_WHI   (SM_XF + 34816)             // 128*264*2 = 67584 B
#define SM_RAW   (SM_WHI + 67584)            // raw fp32 half-tile: 128*128*4 = 65536 B
#define SMEM_TOTAL (SM_RAW + 65536)          // ~170.5 KB

// Scratch (device globals: no allocation allowed)
__device__ float g_scores[N_MAX];   // scores, then exp(s-max) after k3
__device__ float g_stats[2];        // [0] = global max, [1] = sum of exp
__device__ int   g_batch64;         // 1 if batch buffer is int64, 0 if int32

// ===========================================================================
// Warp MMA + ldmatrix + cp.async (baseline PTX, sm_80+)
// ===========================================================================
__device__ __forceinline__ void mma_fp16(float* c,
                                         uint32_t a0, uint32_t a1,
                                         uint32_t a2, uint32_t a3,
                                         uint32_t b0, uint32_t b1)
{
    asm volatile(
        "mma.sync.aligned.m16n8k16.row.col.f32.f16.f16.f32 "
        "{%0,%1,%2,%3}, {%4,%5,%6,%7}, {%8,%9}, {%0,%1,%2,%3};"
        : "+f"(c[0]), "+f"(c[1]), "+f"(c[2]), "+f"(c[3])
        : "r"(a0), "r"(a1), "r"(a2), "r"(a3), "r"(b0), "r"(b1));
}

__device__ __forceinline__ void ldmatrix_x4(uint32_t* r, uint32_t addr)
{
    asm volatile(
        "ldmatrix.sync.aligned.m8n8.x4.shared.b16 {%0,%1,%2,%3}, [%4];"
        : "=r"(r[0]), "=r"(r[1]), "=r"(r[2]), "=r"(r[3]) : "r"(addr));
}

#define CP_ASYNC16(dst, src) \
    asm volatile("cp.async.cg.shared.global [%0], [%1], 16;" \
                 :: "r"(dst), "l"(src) : "memory")
#define CP_COMMIT()  asm volatile("cp.async.commit_group;" ::: "memory")
#define CP_WAIT0()   asm volatile("cp.async.wait_group 0;" ::: "memory")

__device__ void atomicMaxFloat(float* addr, float v)
{
    int* ai  = (int*)addr;
    int  old = *ai;
    while (__int_as_float(old) < v) {
        int assumed = old;
        old = atomicCAS(ai, assumed, __float_as_int(v));
        if (old == assumed) break;
    }
}

// ===========================================================================
// K0: zero output, init stats, detect batch dtype
// int64 layout: int-index N-1 (odd) is the HIGH word of an element -> 0.
// int32 layout: it's the last sorted batch id -> ~511 (nonzero).
// ===========================================================================
__global__ void k0_init(float* __restrict__ out, int out_size,
                        const int* __restrict__ batch_raw, int N)
{
    int idx = blockIdx.x * blockDim.x + threadIdx.x;
    int stride = gridDim.x * blockDim.x;
    for (int i = idx; i < out_size; i += stride) out[i] = 0.0f;
    if (idx == 0) {
        g_stats[0] = -1e30f;
        g_stats[1] = 0.0f;
        g_batch64 = (batch_raw[N - 1] == 0) ? 1 : 0;
    }
}

// ===========================================================================
// K1: scores = relu(x @ W1 + b1) @ W2, warp-mma fp16 (x fp16, W1 fp16).
// UNCHANGED from round 9 (measured at its HMMA-throughput roofline).
// ===========================================================================
extern __shared__ char k1s[];

__global__ __launch_bounds__(K1_THREADS, 1)
void k1_scores(const float* __restrict__ x,
               const float* __restrict__ W1,
               const float* __restrict__ b1,
               const float* __restrict__ W2,
               int N)
{
    int tid  = threadIdx.x;
    int wid  = tid >> 5;
    int lane = tid & 31;
    int g    = lane >> 2;     // group id 0..7
    int t    = lane & 3;      // thread-in-group 0..3
    int wm   = wid >> 2;      // 0..1  -> rows wm*64
    int wn   = wid & 3;       // 0..3  -> cols wn*32

    float*  ps   = (float*)(k1s + SM_PS);
    float*  smax = (float*)(k1s + SM_SMAX);
    float*  b1s  = (float*)(k1s + SM_B1);
    float*  W2s  = (float*)(k1s + SM_W2);
    __half* xf   = (__half*)(k1s + SM_XF);
    __half* whi  = (__half*)(k1s + SM_WHI);
    float*  raw  = (float*)(k1s + SM_RAW);

    uint32_t sbase = (uint32_t)__cvta_generic_to_shared(k1s);

    if (tid < H_HID) { b1s[tid] = b1[tid]; W2s[tid] = W2[tid]; }
    if (tid == 0) *smax = -1e30f;

    // --- Convert W1^T into whi fp16 smem (once). wT[n][k] = W1[k*H+n] ---
    for (int i = tid; i < D_IN * H_HID; i += K1_THREADS) {
        int n = i & 127;
        int k = i >> 7;
        whi[n * WS_STRIDE + k] = __float2half_rn(W1[k * H_HID + n]);
    }

    // --- ldmatrix per-lane address offsets (bytes, excluding k offset) ---
    int ri = lane & 7;        // row within 8x8 tile
    int q  = lane >> 3;       // quadrant 0..3
    int a_off[4];
#pragma unroll
    for (int mt = 0; mt < 4; mt++) {
        int row = wm * 64 + mt * 16 + ri + (q & 1) * 8;
        a_off[mt] = row * XS_STRIDE * 2 + ((q >> 1) * 8) * 2;
    }
    int b_off[2];
#pragma unroll
    for (int j = 0; j < 2; j++) {
        int nt = 2 * j + (q >> 1);
        int nrow = wn * 32 + nt * 8 + ri;
        b_off[j] = nrow * WS_STRIDE * 2 + ((q & 1) * 8) * 2;
    }

    int ntiles = (N + TILE_M - 1) / TILE_M;

    // issue cp.async for a half-tile into raw (16 chunks of 16B per thread)
    auto issue_raw = [&](int row0, int half) {
#pragma unroll
        for (int it = 0; it < (TILE_M * (KHALF / 4)) / K1_THREADS; it++) {
            int i  = it * K1_THREADS + tid;
            int r  = i >> 5;
            int c4 = i & 31;
            int gr = row0 + r;
            uint32_t dst = sbase + SM_RAW + (uint32_t)i * 16;
            if (gr < N) {
                const float* src = x + (size_t)gr * D_IN + half * KHALF + c4 * 4;
                CP_ASYNC16(dst, src);
            } else {
                *(float4*)(raw + i * 4) = make_float4(0.f, 0.f, 0.f, 0.f);
            }
        }
        CP_COMMIT();
    };

    // convert raw fp32 -> xf fp16 (each thread owns the same chunks it issued)
    auto convert = [&]() {
#pragma unroll
        for (int it = 0; it < (TILE_M * (KHALF / 4)) / K1_THREADS; it++) {
            int i  = it * K1_THREADS + tid;
            int r  = i >> 5;
            int c4 = i & 31;
            float4 v = *(const float4*)(raw + i * 4);
            __half2 h01 = __floats2half2_rn(v.x, v.y);
            __half2 h23 = __floats2half2_rn(v.z, v.w);
            *(uint2*)(xf + r * XS_STRIDE + c4 * 4) =
                make_uint2(*(uint32_t*)&h01, *(uint32_t*)&h23);
        }
    };

    // prologue: start loading first half-tile
    int tile = blockIdx.x;
    if (tile < ntiles) issue_raw(tile * TILE_M, 0);

    float lmax = -1e30f;

    for (; tile < ntiles; tile += gridDim.x) {
        int row0 = tile * TILE_M;

        float C[4][4][4];
#pragma unroll
        for (int mt = 0; mt < 4; mt++)
#pragma unroll
            for (int nt = 0; nt < 4; nt++)
#pragma unroll
                for (int qq = 0; qq < 4; qq++) C[mt][nt][qq] = 0.0f;

        for (int half = 0; half < 2; half++) {
            // raw[this half] arrived; previous MMA readers of xf are done
            CP_WAIT0();
            __syncthreads();
            convert();
            __syncthreads();   // xf visible to all warps (raw fully consumed)

            // start async load of the NEXT half (raw is free now)
            int ptile = (half == 0) ? tile : (tile + (int)gridDim.x);
            if (ptile < ntiles) issue_raw(ptile * TILE_M, half ^ 1);

            int kB0 = half * KHALF;

#pragma unroll 2
            for (int ks = 0; ks < 8; ks++) {
                int ka = ks * 16;
                int kb = kB0 + ka;

                uint32_t A[4][4];
#pragma unroll
                for (int mt = 0; mt < 4; mt++)
                    ldmatrix_x4(A[mt], sbase + SM_XF + a_off[mt] + ka * 2);

                uint32_t BH[2][4];
#pragma unroll
                for (int j = 0; j < 2; j++)
                    ldmatrix_x4(BH[j], sbase + SM_WHI + b_off[j] + kb * 2);

#pragma unroll
                for (int j = 0; j < 2; j++)
#pragma unroll
                    for (int jj = 0; jj < 2; jj++) {
                        int nt = 2 * j + jj;
                        uint32_t bh0 = BH[j][2 * jj], bh1 = BH[j][2 * jj + 1];
#pragma unroll
                        for (int mt = 0; mt < 4; mt++)
                            mma_fp16(C[mt][nt], A[mt][0], A[mt][1], A[mt][2], A[mt][3], bh0, bh1);
                    }
            }
        }

        // --- Epilogue: relu(h + b1) dot W2, quad reduce, cross-warp combine ---
        float pAv[4], pBv[4];
#pragma unroll
        for (int mt = 0; mt < 4; mt++) {
            float pa = 0.0f, pb = 0.0f;
#pragma unroll
            for (int nt = 0; nt < 4; nt++) {
                int c0 = wn * 32 + nt * 8 + 2 * t;
                float bb0 = b1s[c0], bb1 = b1s[c0 + 1];
                float ww0 = W2s[c0], ww1 = W2s[c0 + 1];
                float h;
                h = C[mt][nt][0] + bb0; h = h > 0.f ? h : 0.f; pa = fmaf(h, ww0, pa);
                h = C[mt][nt][1] + bb1; h = h > 0.f ? h : 0.f; pa = fmaf(h, ww1, pa);
                h = C[mt][nt][2] + bb0; h = h > 0.f ? h : 0.f; pb = fmaf(h, ww0, pb);
                h = C[mt][nt][3] + bb1; h = h > 0.f ? h : 0.f; pb = fmaf(h, ww1, pb);
            }
            pa += __shfl_xor_sync(0xffffffffu, pa, 1);
            pa += __shfl_xor_sync(0xffffffffu, pa, 2);
            pb += __shfl_xor_sync(0xffffffffu, pb, 1);
            pb += __shfl_xor_sync(0xffffffffu, pb, 2);
            pAv[mt] = pa; pBv[mt] = pb;
        }

        if (wn > 0 && t == 0) {
#pragma unroll
            for (int mt = 0; mt < 4; mt++) {
                int rA = wm * 64 + mt * 16 + g;
                ps[(wn - 1) * 128 + rA]     = pAv[mt];
                ps[(wn - 1) * 128 + rA + 8] = pBv[mt];
            }
        }
        __syncthreads();
        if (wn == 0 && t == 0) {
#pragma unroll
            for (int mt = 0; mt < 4; mt++) {
                int rA = wm * 64 + mt * 16 + g;
                float ta = pAv[mt] + ps[rA] + ps[128 + rA] + ps[256 + rA];
                float tb = pBv[mt] + ps[rA + 8] + ps[128 + rA + 8] + ps[256 + rA + 8];
                int gA = row0 + rA, gB = gA + 8;
                if (gA < N) { g_scores[gA] = ta; lmax = fmaxf(lmax, ta); }
                if (gB < N) { g_scores[gB] = tb; lmax = fmaxf(lmax, tb); }
            }
        }
        __syncthreads();   // ps consumed before next tile overwrites
    }

    // --- fold per-CTA max into global max ---
    if (wn == 0 && t == 0) atomicMaxFloat(smax, lmax);
    __syncthreads();
    if (tid == 0) atomicMaxFloat(&g_stats[0], *smax);
}

// ===========================================================================
// K3: u[i] = exp(s[i] - max) written in place; accumulate Z = sum u
// ===========================================================================
__global__ void k3_sumexp(int N)
{
    float gm = g_stats[0];
    float acc = 0.0f;
    int idx = blockIdx.x * blockDim.x + threadIdx.x;
    int stride = gridDim.x * blockDim.x;
    for (int i = idx; i < N; i += stride) {
        float u = expf(g_scores[i] - gm);
        g_scores[i] = u;
        acc += u;
    }
#pragma unroll
    for (int o = 16; o >= 1; o >>= 1)
        acc += __shfl_xor_sync(0xffffffffu, acc, o);
    __shared__ float s[8];
    int warp = threadIdx.x >> 5, lane = threadIdx.x & 31;
    if (lane == 0) s[warp] = acc;
    __syncthreads();
    if (warp == 0) {
        acc = (lane < (blockDim.x >> 5)) ? s[lane] : 0.0f;
#pragma unroll
        for (int o = 4; o >= 1; o >>= 1)
            acc += __shfl_xor_sync(0xffffffffu, acc, o);
        if (lane == 0) atomicAdd(&g_stats[1], acc);
    }
}

// ===========================================================================
// K4: pooled[batch[i], :] += x[i, :] * u[i] / Z   (batch sorted)
// Row loop unrolled x8 with front-batched independent loads (MLP ~8),
// streaming loads for x (no reuse -> bypass L2 persistence).
// ===========================================================================
__device__ __forceinline__ int read_batch_i(const void* batch, int r, int is64)
{
    if (is64) return (int)((const long long*)batch)[r];
    return ((const int*)batch)[r];
}

__global__ __launch_bounds__(D_IN)
void k4_pool(const float* __restrict__ x,
             const void* __restrict__ batch,
             float* __restrict__ out,
               int N, int out_size)
{
    int c = threadIdx.x;
    int is64 = g_batch64;
    float rz = 1.0f / g_stats[1];
    int nb    = gridDim.x;
    int chunk = (N + nb - 1) / nb;
    int r0 = blockIdx.x * chunk;
    int r1 = r0 + chunk;
    if (r1 > N) r1 = N;
    if (r0 >= r1) return;
    int nseg = out_size / D_IN;

    int cur = read_batch_i(batch, r0, is64);
    float acc = 0.0f;

#define FLUSH() do { \
        if ((unsigned)cur < (unsigned)nseg) \
            atomicAdd(out + (size_t)cur * D_IN + c, acc); \
        acc = 0.0f; \
    } while (0)

    int r = r0;
    for (; r + 8 <= r1; r += 8) {
        // front-batched independent loads (8-way MLP)
        float xv[8], w[8];
        int   bb[8];
#pragma unroll
        for (int u = 0; u < 8; u++)
            xv[u] = __ldcs(x + (size_t)(r + u) * D_IN + c);
#pragma unroll
        for (int u = 0; u < 8; u++)
            w[u] = g_scores[r + u];
#pragma unroll
        for (int u = 0; u < 8; u++)
            bb[u] = read_batch_i(batch, r + u, is64);

#pragma unroll
        for (int u = 0; u < 8; u++) {
            if (bb[u] != cur) { FLUSH(); cur = bb[u]; }
            acc = fmaf(xv[u], w[u] * rz, acc);
        }
    }
    for (; r < r1; r++) {
        float xv = __ldcs(x + (size_t)r * D_IN + c);
        float w  = g_scores[r];
        int b = read_batch_i(batch, r, is64);
        if (b != cur) { FLUSH(); cur = b; }
        acc = fmaf(xv, w * rz, acc);
    }
    FLUSH();
#undef FLUSH
}

// ===========================================================================
// Launch
// ===========================================================================
extern "C" void kernel_launch(void* const* d_in, const int* in_sizes, int n_in,
                              void* d_out, int out_size)
{
    const float* x = (const float*)d_in[0];
    const void*  batch = d_in[1];
    int N = in_sizes[1];

    int iW1 = -1;
    for (int i = 2; i < n_in; i++)
        if (in_sizes[i] == D_IN * H_HID) { iW1 = i; break; }
    if (iW1 < 0) iW1 = 2;
    const float* W1 = (const float*)d_in[iW1];
    const float* b1 = (const float*)d_in[iW1 + 1];
    const float* W2 = (const float*)d_in[iW1 + 2];
    // b2 dropped: constant shift is softmax-invariant

    cudaFuncSetAttribute(k1_scores, cudaFuncAttributeMaxDynamicSharedMemorySize,
                         SMEM_TOTAL);

    k0_init<<<512, 256>>>((float*)d_out, out_size, (const int*)batch, N);
    k1_scores<<<148, K1_THREADS, SMEM_TOTAL>>>(x, W1, b1, W2, N);
    k3_sumexp<<<592, 256>>>(N);
    k4_pool<<<2048, D_IN>>>(x, batch, (float*)d_out, N, out_size);
}

// round 12
// speedup vs baseline: 8.4799x; 1.0552x over previous
#include <cuda_runtime.h>
#include <cuda_fp16.h>
#include <cuda_bf16.h>
#include <math.h>
#include <stdint.h>

// ===========================================================================
// Problem constants
// ===========================================================================
#define D_IN   256
#define H_HID  128
#define TILE_M 128
#define KHALF  128
#define N_MAX  302080
#define K1_THREADS 256
#define K4_BLOCKS 8192
#define K4_THREADS 64

#define XS_STRIDE 136     // fp16 elems per x-smem row (128 + 8 pad)
#define WS_STRIDE 264     // fp16 elems per W1t-smem row (256 + 8 pad)

// SMEM layout (byte offsets into dynamic smem)
#define SM_PS    0                           // 384 floats (3 n-warps x 128 rows)
#define SM_SMAX  1536                        // 1 float (+pad)
#define SM_B1    1568                        // 128 floats
#define SM_W2    2080                        // 128 floats
#define SM_XF    2592                        // fp16 x tile: 128*136*2 = 34816 B
#define SM_WHI   (SM_XF + 34816)             // 128*264*2 = 67584 B
#define SM_RAW   (SM_WHI + 67584)            // raw fp32 half-tile: 128*128*4 = 65536 B
#define SMEM_TOTAL (SM_RAW + 65536)          // ~170.5 KB

// Scratch (device globals: no allocation allowed)
__device__ float g_scores[N_MAX];   // scores, then exp(s-max) after k3
__device__ float g_stats[2];        // [0] = global max, [1] = sum of exp
__device__ int   g_batch64;         // 1 if batch buffer is int64, 0 if int32

// ===========================================================================
// Warp MMA + ldmatrix + cp.async (baseline PTX, sm_80+)
// ===========================================================================
__device__ __forceinline__ void mma_fp16(float* c,
                                         uint32_t a0, uint32_t a1,
                                         uint32_t a2, uint32_t a3,
                                         uint32_t b0, uint32_t b1)
{
    asm volatile(
        "mma.sync.aligned.m16n8k16.row.col.f32.f16.f16.f32 "
        "{%0,%1,%2,%3}, {%4,%5,%6,%7}, {%8,%9}, {%0,%1,%2,%3};"
        : "+f"(c[0]), "+f"(c[1]), "+f"(c[2]), "+f"(c[3])
        : "r"(a0), "r"(a1), "r"(a2), "r"(a3), "r"(b0), "r"(b1));
}

__device__ __forceinline__ void ldmatrix_x4(uint32_t* r, uint32_t addr)
{
    asm volatile(
        "ldmatrix.sync.aligned.m8n8.x4.shared.b16 {%0,%1,%2,%3}, [%4];"
        : "=r"(r[0]), "=r"(r[1]), "=r"(r[2]), "=r"(r[3]) : "r"(addr));
}

#define CP_ASYNC16(dst, src) \
    asm volatile("cp.async.cg.shared.global [%0], [%1], 16;" \
                 :: "r"(dst), "l"(src) : "memory")
#define CP_COMMIT()  asm volatile("cp.async.commit_group;" ::: "memory")
#define CP_WAIT0()   asm volatile("cp.async.wait_group 0;" ::: "memory")

__device__ void atomicMaxFloat(float* addr, float v)
{
    int* ai  = (int*)addr;
    int  old = *ai;
    while (__int_as_float(old) < v) {
        int assumed = old;
        old = atomicCAS(ai, assumed, __float_as_int(v));
        if (old == assumed) break;
    }
}

// ===========================================================================
// K0: zero output, init stats, detect batch dtype
// int64 layout: int-index N-1 (odd) is the HIGH word of an element -> 0.
// int32 layout: it's the last sorted batch id -> ~511 (nonzero).
// ===========================================================================
__global__ void k0_init(float* __restrict__ out, int out_size,
                        const int* __restrict__ batch_raw, int N)
{
    int idx = blockIdx.x * blockDim.x + threadIdx.x;
    int stride = gridDim.x * blockDim.x;
    for (int i = idx; i < out_size; i += stride) out[i] = 0.0f;
    if (idx == 0) {
        g_stats[0] = -1e30f;
        g_stats[1] = 0.0f;
        g_batch64 = (batch_raw[N - 1] == 0) ? 1 : 0;
    }
}

// ===========================================================================
// K1: scores = relu(x @ W1 + b1) @ W2, warp-mma fp16 (x fp16, W1 fp16).
// UNCHANGED (measured at/near its HMMA-throughput roofline in R9).
// ===========================================================================
extern __shared__ char k1s[];

__global__ __launch_bounds__(K1_THREADS, 1)
void k1_scores(const float* __restrict__ x,
               const float* __restrict__ W1,
               const float* __restrict__ b1,
               const float* __restrict__ W2,
               int N)
{
    int tid  = threadIdx.x;
    int wid  = tid >> 5;
    int lane = tid & 31;
    int g    = lane >> 2;     // group id 0..7
    int t    = lane & 3;      // thread-in-group 0..3
    int wm   = wid >> 2;      // 0..1  -> rows wm*64
    int wn   = wid & 3;       // 0..3  -> cols wn*32

    float*  ps   = (float*)(k1s + SM_PS);
    float*  smax = (float*)(k1s + SM_SMAX);
    float*  b1s  = (float*)(k1s + SM_B1);
    float*  W2s  = (float*)(k1s + SM_W2);
    __half* xf   = (__half*)(k1s + SM_XF);
    __half* whi  = (__half*)(k1s + SM_WHI);
    float*  raw  = (float*)(k1s + SM_RAW);

    uint32_t sbase = (uint32_t)__cvta_generic_to_shared(k1s);

    if (tid < H_HID) { b1s[tid] = b1[tid]; W2s[tid] = W2[tid]; }
    if (tid == 0) *smax = -1e30f;

    // --- Convert W1^T into whi fp16 smem (once). wT[n][k] = W1[k*H+n] ---
    for (int i = tid; i < D_IN * H_HID; i += K1_THREADS) {
        int n = i & 127;
        int k = i >> 7;
        whi[n * WS_STRIDE + k] = __float2half_rn(W1[k * H_HID + n]);
    }

    // --- ldmatrix per-lane address offsets (bytes, excluding k offset) ---
    int ri = lane & 7;        // row within 8x8 tile
    int q  = lane >> 3;       // quadrant 0..3
    int a_off[4];
#pragma unroll
    for (int mt = 0; mt < 4; mt++) {
        int row = wm * 64 + mt * 16 + ri + (q & 1) * 8;
        a_off[mt] = row * XS_STRIDE * 2 + ((q >> 1) * 8) * 2;
    }
    int b_off[2];
#pragma unroll
    for (int j = 0; j < 2; j++) {
        int nt = 2 * j + (q >> 1);
        int nrow = wn * 32 + nt * 8 + ri;
        b_off[j] = nrow * WS_STRIDE * 2 + ((q & 1) * 8) * 2;
    }

    int ntiles = (N + TILE_M - 1) / TILE_M;

    // issue cp.async for a half-tile into raw (16 chunks of 16B per thread)
    auto issue_raw = [&](int row0, int half) {
#pragma unroll
        for (int it = 0; it < (TILE_M * (KHALF / 4)) / K1_THREADS; it++) {
            int i  = it * K1_THREADS + tid;
            int r  = i >> 5;
            int c4 = i & 31;
            int gr = row0 + r;
            uint32_t dst = sbase + SM_RAW + (uint32_t)i * 16;
            if (gr < N) {
                const float* src = x + (size_t)gr * D_IN + half * KHALF + c4 * 4;
                CP_ASYNC16(dst, src);
            } else {
                *(float4*)(raw + i * 4) = make_float4(0.f, 0.f, 0.f, 0.f);
            }
        }
        CP_COMMIT();
    };

    // convert raw fp32 -> xf fp16 (each thread owns the same chunks it issued)
    auto convert = [&]() {
#pragma unroll
        for (int it = 0; it < (TILE_M * (KHALF / 4)) / K1_THREADS; it++) {
            int i  = it * K1_THREADS + tid;
            int r  = i >> 5;
            int c4 = i & 31;
            float4 v = *(const float4*)(raw + i * 4);
            __half2 h01 = __floats2half2_rn(v.x, v.y);
            __half2 h23 = __floats2half2_rn(v.z, v.w);
            *(uint2*)(xf + r * XS_STRIDE + c4 * 4) =
                make_uint2(*(uint32_t*)&h01, *(uint32_t*)&h23);
        }
    };

    // prologue: start loading first half-tile
    int tile = blockIdx.x;
    if (tile < ntiles) issue_raw(tile * TILE_M, 0);

    float lmax = -1e30f;

    for (; tile < ntiles; tile += gridDim.x) {
        int row0 = tile * TILE_M;

        float C[4][4][4];
#pragma unroll
        for (int mt = 0; mt < 4; mt++)
#pragma unroll
            for (int nt = 0; nt < 4; nt++)
#pragma unroll
                for (int qq = 0; qq < 4; qq++) C[mt][nt][qq] = 0.0f;

        for (int half = 0; half < 2; half++) {
            // raw[this half] arrived; previous MMA readers of xf are done
            CP_WAIT0();
            __syncthreads();
            convert();
            __syncthreads();   // xf visible to all warps (raw fully consumed)

            // start async load of the NEXT half (raw is free now)
            int ptile = (half == 0) ? tile : (tile + (int)gridDim.x);
            if (ptile < ntiles) issue_raw(ptile * TILE_M, half ^ 1);

            int kB0 = half * KHALF;

#pragma unroll 2
            for (int ks = 0; ks < 8; ks++) {
                int ka = ks * 16;
                int kb = kB0 + ka;

                uint32_t A[4][4];
#pragma unroll
                for (int mt = 0; mt < 4; mt++)
                    ldmatrix_x4(A[mt], sbase + SM_XF + a_off[mt] + ka * 2);

                uint32_t BH[2][4];
#pragma unroll
                for (int j = 0; j < 2; j++)
                    ldmatrix_x4(BH[j], sbase + SM_WHI + b_off[j] + kb * 2);

#pragma unroll
                for (int j = 0; j < 2; j++)
#pragma unroll
                    for (int jj = 0; jj < 2; jj++) {
                        int nt = 2 * j + jj;
                        uint32_t bh0 = BH[j][2 * jj], bh1 = BH[j][2 * jj + 1];
#pragma unroll
                        for (int mt = 0; mt < 4; mt++)
                            mma_fp16(C[mt][nt], A[mt][0], A[mt][1], A[mt][2], A[mt][3], bh0, bh1);
                    }
            }
        }

        // --- Epilogue: relu(h + b1) dot W2, quad reduce, cross-warp combine ---
        float pAv[4], pBv[4];
#pragma unroll
        for (int mt = 0; mt < 4; mt++) {
            float pa = 0.0f, pb = 0.0f;
#pragma unroll
            for (int nt = 0; nt < 4; nt++) {
                int c0 = wn * 32 + nt * 8 + 2 * t;
                float bb0 = b1s[c0], bb1 = b1s[c0 + 1];
                float ww0 = W2s[c0], ww1 = W2s[c0 + 1];
                float h;
                h = C[mt][nt][0] + bb0; h = h > 0.f ? h : 0.f; pa = fmaf(h, ww0, pa);
                h = C[mt][nt][1] + bb1; h = h > 0.f ? h : 0.f; pa = fmaf(h, ww1, pa);
                h = C[mt][nt][2] + bb0; h = h > 0.f ? h : 0.f; pb = fmaf(h, ww0, pb);
                h = C[mt][nt][3] + bb1; h = h > 0.f ? h : 0.f; pb = fmaf(h, ww1, pb);
            }
            pa += __shfl_xor_sync(0xffffffffu, pa, 1);
            pa += __shfl_xor_sync(0xffffffffu, pa, 2);
            pb += __shfl_xor_sync(0xffffffffu, pb, 1);
            pb += __shfl_xor_sync(0xffffffffu, pb, 2);
            pAv[mt] = pa; pBv[mt] = pb;
        }

        if (wn > 0 && t == 0) {
#pragma unroll
            for (int mt = 0; mt < 4; mt++) {
                int rA = wm * 64 + mt * 16 + g;
                ps[(wn - 1) * 128 + rA]     = pAv[mt];
                ps[(wn - 1) * 128 + rA + 8] = pBv[mt];
            }
        }
        __syncthreads();
        if (wn == 0 && t == 0) {
#pragma unroll
            for (int mt = 0; mt < 4; mt++) {
                int rA = wm * 64 + mt * 16 + g;
                float ta = pAv[mt] + ps[rA] + ps[128 + rA] + ps[256 + rA];
                float tb = pBv[mt] + ps[rA + 8] + ps[128 + rA + 8] + ps[256 + rA + 8];
                int gA = row0 + rA, gB = gA + 8;
                if (gA < N) { g_scores[gA] = ta; lmax = fmaxf(lmax, ta); }
                if (gB < N) { g_scores[gB] = tb; lmax = fmaxf(lmax, tb); }
            }
        }
        __syncthreads();   // ps consumed before next tile overwrites
    }

    // --- fold per-CTA max into global max ---
    if (wn == 0 && t == 0) atomicMaxFloat(smax, lmax);
    __syncthreads();
    if (tid == 0) atomicMaxFloat(&g_stats[0], *smax);
}

// ===========================================================================
// K3: u[i] = exp(s[i] - max) written in place; accumulate Z = sum u
// ===========================================================================
__global__ void k3_sumexp(int N)
{
    float gm = g_stats[0];
    float acc = 0.0f;
    int idx = blockIdx.x * blockDim.x + threadIdx.x;
    int stride = gridDim.x * blockDim.x;
    for (int i = idx; i < N; i += stride) {
        float u = expf(g_scores[i] - gm);
        g_scores[i] = u;
        acc += u;
    }
#pragma unroll
    for (int o = 16; o >= 1; o >>= 1)
        acc += __shfl_xor_sync(0xffffffffu, acc, o);
    __shared__ float s[8];
    int warp = threadIdx.x >> 5, lane = threadIdx.x & 31;
    if (lane == 0) s[warp] = acc;
    __syncthreads();
    if (warp == 0) {
        acc = (lane < (blockDim.x >> 5)) ? s[lane] : 0.0f;
#pragma unroll
        for (int o = 4; o >= 1; o >>= 1)
            acc += __shfl_xor_sync(0xffffffffu, acc, o);
        if (lane == 0) atomicAdd(&g_stats[1], acc);
    }
}

// ===========================================================================
// K4: pooled[batch[i], :] += x[i, :] * u[i] / Z   (batch sorted)
// 64 threads/block, 4 columns per thread via float4 loads (LDG.128):
// 4x fewer load instructions per byte, 4x fewer redundant scalar loads.
// Unroll x4 with front-batched independent loads.
// ===========================================================================
__device__ __forceinline__ int read_batch_i(const void* batch, int r, int is64)
{
    if (is64) return (int)((const long long*)batch)[r];
    return ((const int*)batch)[r];
}

__global__ __launch_bounds__(K4_THREADS)
void k4_pool(const float* __restrict__ x,
             const void* __restrict__ batch,
             float* __restrict__ out,
             int N, int out_size)
{
    int c = threadIdx.x * 4;     // first of 4 columns owned by this thread
    int is64 = g_batch64;
    float rz = 1.0f / g_stats[1];
    int nb    = gridDim.x;
    int chunk = (N + nb - 1) / nb;
    int r0 = blockIdx.x * chunk;
    int r1 = r0 + chunk;
    if (r1 > N) r1 = N;
    if (r0 >= r1) return;
    int nseg = out_size / D_IN;

    int cur = read_batch_i(batch, r0, is64);
    float ax = 0.f, ay = 0.f, az = 0.f, aw = 0.f;

#define FLUSH() do { \
        if ((unsigned)cur < (unsigned)nseg) { \
            float* o = out + (size_t)cur * D_IN + c; \
            atomicAdd(o + 0, ax); atomicAdd(o + 1, ay); \
            atomicAdd(o + 2, az); atomicAdd(o + 3, aw); \
        } \
        ax = ay = az = aw = 0.f; \
    } while (0)

    int r = r0;
    for (; r + 4 <= r1; r += 4) {
        // front-batched independent loads
        float4 xv[4];
        float  w[4];
        int    bb[4];
#pragma unroll
        for (int u = 0; u < 4; u++)
            xv[u] = *(const float4*)(x + (size_t)(r + u) * D_IN + c);
#pragma unroll
        for (int u = 0; u < 4; u++)
            w[u] = g_scores[r + u];
#pragma unroll
        for (int u = 0; u < 4; u++)
            bb[u] = read_batch_i(batch, r + u, is64);

#pragma unroll
        for (int u = 0; u < 4; u++) {
            if (bb[u] != cur) { FLUSH(); cur = bb[u]; }
            float wu = w[u] * rz;
            ax = fmaf(xv[u].x, wu, ax);
            ay = fmaf(xv[u].y, wu, ay);
            az = fmaf(xv[u].z, wu, az);
            aw = fmaf(xv[u].w, wu, aw);
        }
    }
    for (; r < r1; r++) {
        float4 xv = *(const float4*)(x + (size_t)r * D_IN + c);
        float wu  = g_scores[r] * rz;
        int b = read_batch_i(batch, r, is64);
        if (b != cur) { FLUSH(); cur = b; }
        ax = fmaf(xv.x, wu, ax);
        ay = fmaf(xv.y, wu, ay);
        az = fmaf(xv.z, wu, az);
        aw = fmaf(xv.w, wu, aw);
    }
    FLUSH();
#undef FLUSH
}

// ===========================================================================
// Launch
// ===========================================================================
extern "C" void kernel_launch(void* const* d_in, const int* in_sizes, int n_in,
                              void* d_out, int out_size)
{
    const float* x = (const float*)d_in[0];
    const void*  batch = d_in[1];
    int N = in_sizes[1];

    int iW1 = -1;
    for (int i = 2; i < n_in; i++)
        if (in_sizes[i] == D_IN * H_HID) { iW1 = i; break; }
    if (iW1 < 0) iW1 = 2;
    const float* W1 = (const float*)d_in[iW1];
    const float* b1 = (const float*)d_in[iW1 + 1];
    const float* W2 = (const float*)d_in[iW1 + 2];
    // b2 dropped: constant shift is softmax-invariant

    cudaFuncSetAttribute(k1_scores, cudaFuncAttributeMaxDynamicSharedMemorySize,
                         SMEM_TOTAL);

    k0_init<<<512, 256>>>((float*)d_out, out_size, (const int*)batch, N);
    k1_scores<<<148, K1_THREADS, SMEM_TOTAL>>>(x, W1, b1, W2, N);
    k3_sumexp<<<592, 256>>>(N);
    k4_pool<<<K4_BLOCKS, K4_THREADS>>>(x, batch, (float*)d_out, N, out_size);
}